// round 1
// baseline (speedup 1.0000x reference)
#include <cuda_runtime.h>
#include <math.h>

#define BB 4
#define NN 20000
#define EE 100000
#define CC 128
#define NM 32
#define KTOT 576   // 128 (h) + 384 (g) + 32 (cos) + 32 (sin)

// ---------------- scratch (static device globals; no allocation) -------------
__device__ float d_hA[BB * NN * CC];
__device__ float d_hB[BB * NN * CC];
__device__ float d_g[(size_t)BB * NN * 384];
__device__ float d_cosv[BB * NN * NM];
__device__ float d_sinv[BB * NN * NM];
__device__ float d_xcs[BB * 65 * CC];     // rows: 0..31 cos, 32..63 sin, 64 plain
__device__ float d_specW[BB * 64 * CC];   // rows: 0..31 = 2*fc, 32..63 = -2*fs
__device__ float d_f0[BB * CC];
__device__ float d_wcat[512 * CC];        // [k][o]: k<128 -> ww^T, else gw^T

// ---------------- basis: cos/sin of nodes . (modes*invL) ---------------------
__global__ void basis_kernel(const float* __restrict__ nodes,
                             const float* __restrict__ modes,
                             const float* __restrict__ latent,
                             float* __restrict__ cosv, float* __restrict__ sinv) {
    int idx = blockIdx.x * blockDim.x + threadIdx.x;
    if (idx >= BB * NN) return;
    float il0 = 0.5f + 1.5f / (1.f + expf(-latent[0]));
    float il1 = 0.5f + 1.5f / (1.f + expf(-latent[1]));
    float il2 = 0.5f + 1.5f / (1.f + expf(-latent[2]));
    float n0 = nodes[idx * 3 + 0];
    float n1 = nodes[idx * 3 + 1];
    float n2 = nodes[idx * 3 + 2];
    #pragma unroll
    for (int k = 0; k < NM; k++) {
        float t = n0 * modes[k * 3 + 0] * il0
                + n1 * modes[k * 3 + 1] * il1
                + n2 * modes[k * 3 + 2] * il2;
        float s, c;
        sincosf(t, &s, &c);
        cosv[idx * NM + k] = c;
        sinv[idx * NM + k] = s;
    }
}

// ---------------- fc0: h = x @ fc0_w^T + b -----------------------------------
__global__ void fc0_kernel(const float* __restrict__ x, const float* __restrict__ w,
                           const float* __restrict__ bias, float* __restrict__ h) {
    int idx = blockIdx.x * blockDim.x + threadIdx.x;
    if (idx >= BB * NN * CC) return;
    int c = idx & 127;
    int node = idx >> 7;
    h[idx] = bias[c] + x[node * 3 + 0] * w[c * 3 + 0]
                     + x[node * 3 + 1] * w[c * 3 + 1]
                     + x[node * 3 + 2] * w[c * 3 + 2];
}

// ---------------- forward spectral transform ---------------------------------
// xcs[b,r,c] = sum_n basis_r(b,n)*w(b,n)*h[b,n,c];  r<32 cos, r<64 sin, r==64 ones
#define FCHUNK 125
#define FBLOCKS 160   // 160*125 = 20000
__global__ void forward_kernel(const float* __restrict__ h,
                               const float* __restrict__ cosv,
                               const float* __restrict__ sinv,
                               const float* __restrict__ nw,
                               float* __restrict__ xcs) {
    int b = blockIdx.y;
    int c = threadIdx.x;     // 128 threads
    int n0 = blockIdx.x * FCHUNK;
    int n1 = n0 + FCHUNK;    // exact, no remainder
    float acc[65];
    #pragma unroll
    for (int r = 0; r < 65; r++) acc[r] = 0.f;
    __shared__ float sb[65];
    for (int n = n0; n < n1; n++) {
        float w = nw[b * NN + n];
        if (c < 32)      sb[c] = w * cosv[(b * NN + n) * NM + c];
        else if (c < 64) sb[c] = w * sinv[(b * NN + n) * NM + (c - 32)];
        else if (c == 64) sb[64] = w;
        __syncthreads();
        float hv = h[(b * NN + n) * CC + c];
        #pragma unroll
        for (int r = 0; r < 65; r++) acc[r] += hv * sb[r];
        __syncthreads();
    }
    #pragma unroll
    for (int r = 0; r < 65; r++)
        atomicAdd(&xcs[(b * 65 + r) * CC + c], acc[r]);
}

// ---------------- mode mixing ------------------------------------------------
// specW[b,k,o] = 2*fc; specW[b,32+k,o] = -2*fs; f0[b,o]
__global__ void modemix_kernel(const float* __restrict__ xcs,
                               const float* __restrict__ swc_l,
                               const float* __restrict__ sws_l,
                               const float* __restrict__ sw0_l,
                               float* __restrict__ specW, float* __restrict__ f0) {
    int b = blockIdx.x;
    int k = blockIdx.y;    // 0..32, 32 => f0 path
    int o = threadIdx.x;   // 128
    __shared__ float xc_s[CC], xs_s[CC];
    if (k < 32) {
        xc_s[o] = xcs[(b * 65 + k) * CC + o];
        xs_s[o] = xcs[(b * 65 + 32 + k) * CC + o];
        __syncthreads();
        float fc = 0.f, fs = 0.f;
        for (int c = 0; c < CC; c++) {
            float wc = swc_l[(c * CC + o) * NM + k];
            float ws = sws_l[(c * CC + o) * NM + k];
            float xc = xc_s[c], xs = xs_s[c];
            fc += xc * wc - xs * ws;
            fs += xs * wc + xc * ws;
        }
        specW[(b * 64 + k) * CC + o]      =  2.f * fc;
        specW[(b * 64 + 32 + k) * CC + o] = -2.f * fs;
    } else {
        xc_s[o] = xcs[(b * 65 + 64) * CC + o];
        __syncthreads();
        float f = 0.f;
        for (int c = 0; c < CC; c++) f += xc_s[c] * sw0_l[c * CC + o];
        f0[b * CC + o] = f;
    }
}

// ---------------- concat weight transpose (ww | gw) -> [k][o] ----------------
__global__ void wcat_kernel(const float* __restrict__ ww_l,
                            const float* __restrict__ gw_l,
                            float* __restrict__ wcat) {
    int idx = blockIdx.x * blockDim.x + threadIdx.x;
    if (idx >= 512 * CC) return;
    int k = idx >> 7, o = idx & 127;
    wcat[idx] = (k < 128) ? ww_l[o * CC + k] : gw_l[o * 384 + (k - 128)];
}

// ---------------- gradient scatter -------------------------------------------
#define EPB 64
__global__ void scatter_kernel(const float* __restrict__ h,
                               const int* __restrict__ edges,
                               const float* __restrict__ egw,
                               float* __restrict__ g) {
    int b = blockIdx.y;
    int e0 = blockIdx.x * EPB;
    int tid = threadIdx.x;     // 128
    __shared__ int s_tgt[EPB], s_src[EPB];
    __shared__ float s_w[EPB][3];
    int nE = min(EPB, EE - e0);
    if (tid < nE * 2) {
        int v = edges[((size_t)b * EE + e0) * 2 + tid];
        if (tid & 1) s_src[tid >> 1] = v; else s_tgt[tid >> 1] = v;
    }
    for (int i = tid; i < nE * 3; i += 128)
        s_w[i / 3][i % 3] = egw[((size_t)b * EE + e0) * 3 + i];
    __syncthreads();
    int c = tid;
    for (int e = 0; e < nE; e++) {
        int src = s_src[e], tgt = s_tgt[e];
        float diff = h[(b * NN + src) * CC + c] - h[(b * NN + tgt) * CC + c];
        float* gp = g + (size_t)(b * NN + tgt) * 384 + c * 3;
        atomicAdd(gp + 0, s_w[e][0] * diff);
        atomicAdd(gp + 1, s_w[e][1] * diff);
        atomicAdd(gp + 2, s_w[e][2] * diff);
    }
}

// ---------------- fused combine GEMM + bias + gelu ---------------------------
// out[b,n,o] = sum_{k<576} A[b,n,k]*W[b,k,o] + wb[o]+gb[o]+f0[b,o]; optional gelu
// A = [h(128) | g(384) | cos(32) | sin(32)];  W = [wcat(512) | specW(64, per-b)]
__global__ void __launch_bounds__(256, 2)
combine_kernel(const float* __restrict__ h, const float* __restrict__ g,
               const float* __restrict__ cosv, const float* __restrict__ sinv,
               const float* __restrict__ wcat, const float* __restrict__ specW,
               const float* __restrict__ f0, const float* __restrict__ wb,
               const float* __restrict__ gb, float* __restrict__ hout,
               int gelu_flag) {
    int b = blockIdx.y;
    int n0 = blockIdx.x * 64;
    int tid = threadIdx.x;
    int tx = tid & 31, ty = tid >> 5;     // 32 x 8
    __shared__ float As[64][17];
    __shared__ float Ws[16][128];
    float acc[8][4];
    #pragma unroll
    for (int i = 0; i < 8; i++)
        #pragma unroll
        for (int j = 0; j < 4; j++) acc[i][j] = 0.f;

    for (int kt = 0; kt < 36; kt++) {
        int kbase = kt * 16;
        #pragma unroll
        for (int r = 0; r < 4; r++) {
            int l = tid + r * 256;
            int nl = l >> 4, kk = l & 15;
            int n = n0 + nl;
            int k = kbase + kk;
            float v = 0.f;
            if (n < NN) {
                int base = b * NN + n;
                if (k < 128)      v = h[base * 128 + k];
                else if (k < 512) v = g[(size_t)base * 384 + (k - 128)];
                else if (k < 544) v = cosv[base * 32 + (k - 512)];
                else              v = sinv[base * 32 + (k - 544)];
            }
            As[nl][kk] = v;
        }
        #pragma unroll
        for (int r = 0; r < 8; r++) {
            int l = tid + r * 256;
            int kk = l >> 7, o = l & 127;
            int k = kbase + kk;
            Ws[kk][o] = (k < 512) ? wcat[k * 128 + o]
                                  : specW[(b * 64 + (k - 512)) * 128 + o];
        }
        __syncthreads();
        #pragma unroll
        for (int kk = 0; kk < 16; kk++) {
            float a[8], w[4];
            #pragma unroll
            for (int i = 0; i < 8; i++) a[i] = As[ty + 8 * i][kk];
            #pragma unroll
            for (int j = 0; j < 4; j++) w[j] = Ws[kk][tx + 32 * j];
            #pragma unroll
            for (int i = 0; i < 8; i++)
                #pragma unroll
                for (int j = 0; j < 4; j++) acc[i][j] += a[i] * w[j];
        }
        __syncthreads();
    }
    #pragma unroll
    for (int i = 0; i < 8; i++) {
        int n = n0 + ty + 8 * i;
        if (n >= NN) continue;
        #pragma unroll
        for (int j = 0; j < 4; j++) {
            int o = tx + 32 * j;
            float v = acc[i][j] + wb[o] + gb[o] + f0[b * CC + o];
            if (gelu_flag) v = 0.5f * v * (1.f + erff(v * 0.70710678118654752f));
            hout[(b * NN + n) * CC + o] = v;
        }
    }
}

// ---------------- final MLP: gelu(h@fc1^T+b1)@fc2^T+b2 -----------------------
__global__ void final_kernel(const float* __restrict__ h,
                             const float* __restrict__ fc1_w,
                             const float* __restrict__ fc1_b,
                             const float* __restrict__ fc2_w,
                             const float* __restrict__ fc2_b,
                             float* __restrict__ out) {
    int node = blockIdx.x;   // B*N blocks
    int j = threadIdx.x;     // 128
    __shared__ float hs[CC];
    __shared__ float red[4];
    hs[j] = h[node * CC + j];
    __syncthreads();
    float acc = fc1_b[j];
    #pragma unroll 4
    for (int c = 0; c < CC; c++) acc += hs[c] * fc1_w[j * CC + c];
    acc = 0.5f * acc * (1.f + erff(acc * 0.70710678118654752f));
    acc *= fc2_w[j];
    #pragma unroll
    for (int off = 16; off; off >>= 1)
        acc += __shfl_down_sync(0xffffffffu, acc, off);
    if ((j & 31) == 0) red[j >> 5] = acc;
    __syncthreads();
    if (j == 0) out[node] = red[0] + red[1] + red[2] + red[3] + fc2_b[0];
}

// ---------------- launcher ----------------------------------------------------
extern "C" void kernel_launch(void* const* d_in, const int* in_sizes, int n_in,
                              void* d_out, int out_size) {
    const float* x      = (const float*)d_in[0];
    // d_in[1] = node_mask (unused by reference)
    const float* nodes  = (const float*)d_in[2];
    const float* nw     = (const float*)d_in[3];
    const int*   edges  = (const int*)  d_in[4];
    const float* egw    = (const float*)d_in[5];
    const float* modes  = (const float*)d_in[6];
    const float* latent = (const float*)d_in[7];
    const float* fc0_w  = (const float*)d_in[8];
    const float* fc0_b  = (const float*)d_in[9];
    const float* swc    = (const float*)d_in[10];
    const float* sws    = (const float*)d_in[11];
    const float* sw0    = (const float*)d_in[12];
    const float* ww     = (const float*)d_in[13];
    const float* wb     = (const float*)d_in[14];
    const float* gw     = (const float*)d_in[15];
    const float* gb     = (const float*)d_in[16];
    const float* fc1_w  = (const float*)d_in[17];
    const float* fc1_b  = (const float*)d_in[18];
    const float* fc2_w  = (const float*)d_in[19];
    const float* fc2_b  = (const float*)d_in[20];
    float* out = (float*)d_out;

    float *hA, *hB, *g, *cosv, *sinv, *xcs, *specW, *f0, *wcat;
    cudaGetSymbolAddress((void**)&hA,    d_hA);
    cudaGetSymbolAddress((void**)&hB,    d_hB);
    cudaGetSymbolAddress((void**)&g,     d_g);
    cudaGetSymbolAddress((void**)&cosv,  d_cosv);
    cudaGetSymbolAddress((void**)&sinv,  d_sinv);
    cudaGetSymbolAddress((void**)&xcs,   d_xcs);
    cudaGetSymbolAddress((void**)&specW, d_specW);
    cudaGetSymbolAddress((void**)&f0,    d_f0);
    cudaGetSymbolAddress((void**)&wcat,  d_wcat);

    basis_kernel<<<(BB * NN + 127) / 128, 128>>>(nodes, modes, latent, cosv, sinv);
    fc0_kernel<<<(BB * NN * CC + 255) / 256, 256>>>(x, fc0_w, fc0_b, hA);

    float* hin = hA;
    float* hout = hB;
    for (int l = 0; l < 3; l++) {
        cudaMemsetAsync(xcs, 0, (size_t)BB * 65 * CC * sizeof(float), 0);
        forward_kernel<<<dim3(FBLOCKS, BB), 128>>>(hin, cosv, sinv, nw, xcs);
        modemix_kernel<<<dim3(BB, 33), 128>>>(
            xcs,
            swc + (size_t)l * CC * CC * NM,
            sws + (size_t)l * CC * CC * NM,
            sw0 + (size_t)l * CC * CC,
            specW, f0);
        wcat_kernel<<<(512 * CC + 255) / 256, 256>>>(
            ww + (size_t)l * CC * CC, gw + (size_t)l * CC * 384, wcat);
        cudaMemsetAsync(g, 0, (size_t)BB * NN * 384 * sizeof(float), 0);
        scatter_kernel<<<dim3((EE + EPB - 1) / EPB, BB), 128>>>(hin, edges, egw, g);
        combine_kernel<<<dim3((NN + 63) / 64, BB), 256>>>(
            hin, g, cosv, sinv, wcat, specW, f0,
            wb + l * CC, gb + l * CC, hout, (l < 2) ? 1 : 0);
        float* t = hin; hin = hout; hout = t;
    }
    final_kernel<<<BB * NN, 128>>>(hin, fc1_w, fc1_b, fc2_w, fc2_b, out);
}

// round 2
// speedup vs baseline: 3.0071x; 3.0071x over previous
#include <cuda_runtime.h>
#include <math.h>

#define BB 4
#define NN 20000
#define EE 100000
#define CC 128
#define NM 32
#define KTOT 576   // 128 (h) + 384 (g) + 32 (cos) + 32 (sin)

// ---------------- scratch (static device globals; no allocation) -------------
__device__ float d_hA[BB * NN * CC];
__device__ float d_hB[BB * NN * CC];
__device__ float d_g[(size_t)BB * NN * 384];
__device__ float d_cosv[BB * NN * NM];
__device__ float d_sinv[BB * NN * NM];
__device__ float d_xcs[BB * 65 * CC];
__device__ float d_specW[BB * 64 * CC];
__device__ float d_f0[BB * CC];
__device__ float d_wcat[512 * CC];
__device__ float d_wtc[NM * CC * CC];     // [k][c][o]
__device__ float d_wts[NM * CC * CC];     // [k][c][o]
__device__ float d_fc1wt[CC * CC];        // [c][j]
// CSR scratch
__device__ int   d_count[BB * NN];
__device__ int   d_cursor[BB * NN];
__device__ int   d_offsets[BB * (NN + 1)];
__device__ int   d_esrc[BB * EE];
__device__ float d_ew3[(size_t)BB * EE * 3];

__device__ __forceinline__ float gelu_f(float v) {
    return 0.5f * v * (1.f + erff(v * 0.70710678118654752f));
}

// ---------------- basis ------------------------------------------------------
__global__ void basis_kernel(const float* __restrict__ nodes,
                             const float* __restrict__ modes,
                             const float* __restrict__ latent,
                             float* __restrict__ cosv, float* __restrict__ sinv) {
    int idx = blockIdx.x * blockDim.x + threadIdx.x;
    if (idx >= BB * NN) return;
    float il0 = 0.5f + 1.5f / (1.f + expf(-latent[0]));
    float il1 = 0.5f + 1.5f / (1.f + expf(-latent[1]));
    float il2 = 0.5f + 1.5f / (1.f + expf(-latent[2]));
    float n0 = nodes[idx * 3 + 0];
    float n1 = nodes[idx * 3 + 1];
    float n2 = nodes[idx * 3 + 2];
    #pragma unroll
    for (int k = 0; k < NM; k++) {
        float t = n0 * modes[k * 3 + 0] * il0
                + n1 * modes[k * 3 + 1] * il1
                + n2 * modes[k * 3 + 2] * il2;
        float s, c;
        sincosf(t, &s, &c);
        cosv[idx * NM + k] = c;
        sinv[idx * NM + k] = s;
    }
}

// ---------------- fc0 --------------------------------------------------------
__global__ void fc0_kernel(const float* __restrict__ x, const float* __restrict__ w,
                           const float* __restrict__ bias, float* __restrict__ h) {
    int idx = blockIdx.x * blockDim.x + threadIdx.x;
    if (idx >= BB * NN * CC) return;
    int c = idx & 127;
    int node = idx >> 7;
    h[idx] = bias[c] + x[node * 3 + 0] * w[c * 3 + 0]
                     + x[node * 3 + 1] * w[c * 3 + 1]
                     + x[node * 3 + 2] * w[c * 3 + 2];
}

// ---------------- CSR build --------------------------------------------------
__global__ void hist_kernel(const int* __restrict__ edges, int* __restrict__ count) {
    int idx = blockIdx.x * blockDim.x + threadIdx.x;
    if (idx >= BB * EE) return;
    int b = idx / EE;
    int tgt = edges[idx * 2 + 0];
    atomicAdd(&count[b * NN + tgt], 1);
}

__global__ void scan_kernel(const int* __restrict__ count, int* __restrict__ offsets) {
    int b = blockIdx.x;
    int t = threadIdx.x;              // 1024
    __shared__ int sums[1024];
    const int CH = 20;                // 1024*20 = 20480 >= NN
    int base = t * CH;
    int s = 0;
    for (int i = 0; i < CH; i++) {
        int n = base + i;
        if (n < NN) s += count[b * NN + n];
    }
    sums[t] = s;
    __syncthreads();
    for (int off = 1; off < 1024; off <<= 1) {
        int v = (t >= off) ? sums[t - off] : 0;
        __syncthreads();
        sums[t] += v;
        __syncthreads();
    }
    int run = (t == 0) ? 0 : sums[t - 1];
    for (int i = 0; i < CH; i++) {
        int n = base + i;
        if (n < NN) {
            offsets[b * (NN + 1) + n] = run;
            run += count[b * NN + n];
        }
    }
    if (t == 1023) offsets[b * (NN + 1) + NN] = sums[1023];
}

__global__ void fill_kernel(const int* __restrict__ edges, const float* __restrict__ egw,
                            const int* __restrict__ offsets, int* __restrict__ cursor,
                            int* __restrict__ esrc, float* __restrict__ ew3) {
    int idx = blockIdx.x * blockDim.x + threadIdx.x;
    if (idx >= BB * EE) return;
    int b = idx / EE;
    int tgt = edges[idx * 2 + 0];
    int src = edges[idx * 2 + 1];
    int pos = offsets[b * (NN + 1) + tgt] + atomicAdd(&cursor[b * NN + tgt], 1);
    int gp = b * EE + pos;
    esrc[gp] = src;
    ew3[(size_t)gp * 3 + 0] = egw[(size_t)idx * 3 + 0];
    ew3[(size_t)gp * 3 + 1] = egw[(size_t)idx * 3 + 1];
    ew3[(size_t)gp * 3 + 2] = egw[(size_t)idx * 3 + 2];
}

// ---------------- gradient gather (no atomics) -------------------------------
__global__ void gather_kernel(const float* __restrict__ h,
                              const int* __restrict__ offsets,
                              const int* __restrict__ esrc,
                              const float* __restrict__ ew3,
                              float* __restrict__ g) {
    int n = blockIdx.x;
    int b = blockIdx.y;
    int c = threadIdx.x;   // 128
    int o0 = offsets[b * (NN + 1) + n];
    int o1 = offsets[b * (NN + 1) + n + 1];
    float ht = h[(b * NN + n) * CC + c];
    float a0 = 0.f, a1 = 0.f, a2 = 0.f;
    for (int j = o0; j < o1; j++) {
        int src = esrc[b * EE + j];
        float hs = h[(b * NN + src) * CC + c];
        float d = hs - ht;
        a0 += ew3[(size_t)(b * EE + j) * 3 + 0] * d;
        a1 += ew3[(size_t)(b * EE + j) * 3 + 1] * d;
        a2 += ew3[(size_t)(b * EE + j) * 3 + 2] * d;
    }
    size_t gb_ = (size_t)(b * NN + n) * 384 + c * 3;
    g[gb_ + 0] = a0;
    g[gb_ + 1] = a1;
    g[gb_ + 2] = a2;
}

// ---------------- forward spectral transform (8-node staging) ----------------
#define FCHUNK 80
__global__ void forward_kernel(const float* __restrict__ h,
                               const float* __restrict__ cosv,
                               const float* __restrict__ sinv,
                               const float* __restrict__ nw,
                               float* __restrict__ xcs) {
    int b = blockIdx.y;
    int c = threadIdx.x;     // 128
    int n0 = blockIdx.x * FCHUNK;
    float acc[65];
    #pragma unroll
    for (int r = 0; r < 65; r++) acc[r] = 0.f;
    __shared__ float sb[8][65];
    for (int base = n0; base < n0 + FCHUNK; base += 8) {
        for (int l = c; l < 520; l += 128) {
            int i = l / 65;
            int r = l - i * 65;
            int node = base + i;
            float w = nw[b * NN + node];
            float v;
            if (r < 32)      v = w * cosv[(b * NN + node) * NM + r];
            else if (r < 64) v = w * sinv[(b * NN + node) * NM + (r - 32)];
            else             v = w;
            sb[i][r] = v;
        }
        __syncthreads();
        #pragma unroll
        for (int i = 0; i < 8; i++) {
            float hv = h[(b * NN + base + i) * CC + c];
            #pragma unroll
            for (int r = 0; r < 65; r++) acc[r] += hv * sb[i][r];
        }
        __syncthreads();
    }
    #pragma unroll
    for (int r = 0; r < 65; r++)
        atomicAdd(&xcs[(b * 65 + r) * CC + c], acc[r]);
}

// ---------------- weight transposes ------------------------------------------
__global__ void transpose_w_kernel(const float* __restrict__ src, float* __restrict__ dst) {
    int idx = blockIdx.x * blockDim.x + threadIdx.x;
    if (idx >= CC * CC * NM) return;   // idx = (c*128+o)*32+k
    int k = idx & 31;
    int co = idx >> 5;
    int o = co & 127;
    int c = co >> 7;
    dst[(k * CC + c) * CC + o] = src[idx];
}

__global__ void transpose_fc1_kernel(const float* __restrict__ src, float* __restrict__ dst) {
    int idx = blockIdx.x * blockDim.x + threadIdx.x;
    if (idx >= CC * CC) return;        // idx = j*128+c
    int c = idx & 127;
    int j = idx >> 7;
    dst[c * CC + j] = src[idx];
}

// ---------------- mode mixing (coalesced) ------------------------------------
__global__ void modemix_kernel(const float* __restrict__ xcs,
                               const float* __restrict__ wtc,
                               const float* __restrict__ wts,
                               const float* __restrict__ sw0_l,
                               float* __restrict__ specW, float* __restrict__ f0) {
    int b = blockIdx.x;
    int k = blockIdx.y;    // 0..32; 32 => f0
    int o = threadIdx.x;   // 128
    __shared__ float xc_s[CC], xs_s[CC];
    if (k < 32) {
        xc_s[o] = xcs[(b * 65 + k) * CC + o];
        xs_s[o] = xcs[(b * 65 + 32 + k) * CC + o];
        __syncthreads();
        float fc = 0.f, fs = 0.f;
        #pragma unroll 4
        for (int c = 0; c < CC; c++) {
            float wc = wtc[(k * CC + c) * CC + o];
            float ws = wts[(k * CC + c) * CC + o];
            float a = xc_s[c], s2 = xs_s[c];
            fc += a * wc - s2 * ws;
            fs += s2 * wc + a * ws;
        }
        specW[(b * 64 + k) * CC + o]      =  2.f * fc;
        specW[(b * 64 + 32 + k) * CC + o] = -2.f * fs;
    } else {
        xc_s[o] = xcs[(b * 65 + 64) * CC + o];
        __syncthreads();
        float f = 0.f;
        #pragma unroll 4
        for (int c = 0; c < CC; c++) f += xc_s[c] * sw0_l[c * CC + o];
        f0[b * CC + o] = f;
    }
}

// ---------------- concat weight transpose ------------------------------------
__global__ void wcat_kernel(const float* __restrict__ ww_l,
                            const float* __restrict__ gw_l,
                            float* __restrict__ wcat) {
    int idx = blockIdx.x * blockDim.x + threadIdx.x;
    if (idx >= 512 * CC) return;
    int k = idx >> 7, o = idx & 127;
    wcat[idx] = (k < 128) ? ww_l[o * CC + k] : gw_l[o * 384 + (k - 128)];
}

// ---------------- fused combine GEMM (128x128 tile, 8x8 micro) ---------------
__global__ void __launch_bounds__(256, 2)
combine_kernel(const float* __restrict__ h, const float* __restrict__ g,
               const float* __restrict__ cosv, const float* __restrict__ sinv,
               const float* __restrict__ wcat, const float* __restrict__ specW,
               const float* __restrict__ f0, const float* __restrict__ wb,
               const float* __restrict__ gb, float* __restrict__ hout,
               int gelu_flag) {
    int b = blockIdx.y;
    int n0 = blockIdx.x * 128;
    int tid = threadIdx.x;
    int tx = tid & 15, ty = tid >> 4;     // 16 x 16
    __shared__ float As[128][17];
    __shared__ float Ws[16][128];
    float acc[8][8];
    #pragma unroll
    for (int i = 0; i < 8; i++)
        #pragma unroll
        for (int j = 0; j < 8; j++) acc[i][j] = 0.f;

    for (int kt = 0; kt < 36; kt++) {
        int kbase = kt * 16;
        #pragma unroll
        for (int r = 0; r < 8; r++) {
            int l = tid + r * 256;
            int nl = l >> 4, kk = l & 15;
            int n = n0 + nl;
            int k = kbase + kk;
            float v = 0.f;
            if (n < NN) {
                int base = b * NN + n;
                if (k < 128)      v = h[base * 128 + k];
                else if (k < 512) v = g[(size_t)base * 384 + (k - 128)];
                else if (k < 544) v = cosv[base * 32 + (k - 512)];
                else              v = sinv[base * 32 + (k - 544)];
            }
            As[nl][kk] = v;
        }
        #pragma unroll
        for (int r = 0; r < 8; r++) {
            int l = tid + r * 256;
            int kk = l >> 7, o = l & 127;
            int k = kbase + kk;
            Ws[kk][o] = (k < 512) ? wcat[k * 128 + o]
                                  : specW[(b * 64 + (k - 512)) * 128 + o];
        }
        __syncthreads();
        #pragma unroll
        for (int kk = 0; kk < 16; kk++) {
            float a[8];
            #pragma unroll
            for (int i = 0; i < 8; i++) a[i] = As[ty + 16 * i][kk];
            float4 w0 = *(const float4*)&Ws[kk][tx * 4];
            float4 w1 = *(const float4*)&Ws[kk][64 + tx * 4];
            float w[8] = {w0.x, w0.y, w0.z, w0.w, w1.x, w1.y, w1.z, w1.w};
            #pragma unroll
            for (int i = 0; i < 8; i++)
                #pragma unroll
                for (int j = 0; j < 8; j++) acc[i][j] += a[i] * w[j];
        }
        __syncthreads();
    }
    #pragma unroll
    for (int i = 0; i < 8; i++) {
        int n = n0 + ty + 16 * i;
        if (n >= NN) continue;
        #pragma unroll
        for (int j = 0; j < 8; j++) {
            int o = (j < 4) ? (tx * 4 + j) : (64 + tx * 4 + (j - 4));
            float v = acc[i][j] + wb[o] + gb[o] + f0[b * CC + o];
            if (gelu_flag) v = gelu_f(v);
            hout[(b * NN + n) * CC + o] = v;
        }
    }
}

// ---------------- final fused MLP GEMM ---------------------------------------
__global__ void __launch_bounds__(256, 2)
final_gemm(const float* __restrict__ h, const float* __restrict__ fc1wt,
           const float* __restrict__ fc1_b, const float* __restrict__ fc2_w,
           const float* __restrict__ fc2_b, float* __restrict__ out) {
    int m0 = blockIdx.x * 128;           // M = BB*NN = 80000, divisible by 128? 80000/128=625 exact
    int tid = threadIdx.x;
    int tx = tid & 15, ty = tid >> 4;
    __shared__ float As[128][17];
    __shared__ float Ws[16][128];
    float acc[8][8];
    #pragma unroll
    for (int i = 0; i < 8; i++)
        #pragma unroll
        for (int j = 0; j < 8; j++) acc[i][j] = 0.f;

    for (int kt = 0; kt < 8; kt++) {
        int kbase = kt * 16;
        #pragma unroll
        for (int r = 0; r < 8; r++) {
            int l = tid + r * 256;
            int nl = l >> 4, kk = l & 15;
            As[nl][kk] = h[(m0 + nl) * CC + kbase + kk];
        }
        #pragma unroll
        for (int r = 0; r < 8; r++) {
            int l = tid + r * 256;
            int kk = l >> 7, o = l & 127;
            Ws[kk][o] = fc1wt[(kbase + kk) * CC + o];
        }
        __syncthreads();
        #pragma unroll
        for (int kk = 0; kk < 16; kk++) {
            float a[8];
            #pragma unroll
            for (int i = 0; i < 8; i++) a[i] = As[ty + 16 * i][kk];
            float4 w0 = *(const float4*)&Ws[kk][tx * 4];
            float4 w1 = *(const float4*)&Ws[kk][64 + tx * 4];
            float w[8] = {w0.x, w0.y, w0.z, w0.w, w1.x, w1.y, w1.z, w1.w};
            #pragma unroll
            for (int i = 0; i < 8; i++)
                #pragma unroll
                for (int j = 0; j < 8; j++) acc[i][j] += a[i] * w[j];
        }
        __syncthreads();
    }
    // epilogue: gelu, dot with fc2_w, reduce over o
    float part[8];
    #pragma unroll
    for (int i = 0; i < 8; i++) {
        float p = 0.f;
        #pragma unroll
        for (int j = 0; j < 8; j++) {
            int o = (j < 4) ? (tx * 4 + j) : (64 + tx * 4 + (j - 4));
            float v = acc[i][j] + fc1_b[o];
            v = gelu_f(v);
            p += v * fc2_w[o];
        }
        part[i] = p;
    }
    __syncthreads();
    #pragma unroll
    for (int i = 0; i < 8; i++) As[ty + 16 * i][tx] = part[i];
    __syncthreads();
    if (tid < 128) {
        float s = 0.f;
        #pragma unroll
        for (int t = 0; t < 16; t++) s += As[tid][t];
        out[m0 + tid] = s + fc2_b[0];
    }
}

// ---------------- launcher ----------------------------------------------------
extern "C" void kernel_launch(void* const* d_in, const int* in_sizes, int n_in,
                              void* d_out, int out_size) {
    const float* x      = (const float*)d_in[0];
    const float* nodes  = (const float*)d_in[2];
    const float* nw     = (const float*)d_in[3];
    const int*   edges  = (const int*)  d_in[4];
    const float* egw    = (const float*)d_in[5];
    const float* modes  = (const float*)d_in[6];
    const float* latent = (const float*)d_in[7];
    const float* fc0_w  = (const float*)d_in[8];
    const float* fc0_b  = (const float*)d_in[9];
    const float* swc    = (const float*)d_in[10];
    const float* sws    = (const float*)d_in[11];
    const float* sw0    = (const float*)d_in[12];
    const float* ww     = (const float*)d_in[13];
    const float* wb     = (const float*)d_in[14];
    const float* gw     = (const float*)d_in[15];
    const float* gb     = (const float*)d_in[16];
    const float* fc1_w  = (const float*)d_in[17];
    const float* fc1_b  = (const float*)d_in[18];
    const float* fc2_w  = (const float*)d_in[19];
    const float* fc2_b  = (const float*)d_in[20];
    float* out = (float*)d_out;

    float *hA, *hB, *g, *cosv, *sinv, *xcs, *specW, *f0, *wcat, *wtc, *wts, *fc1wt, *ew3;
    int *count, *cursor, *offsets, *esrc;
    cudaGetSymbolAddress((void**)&hA,      d_hA);
    cudaGetSymbolAddress((void**)&hB,      d_hB);
    cudaGetSymbolAddress((void**)&g,       d_g);
    cudaGetSymbolAddress((void**)&cosv,    d_cosv);
    cudaGetSymbolAddress((void**)&sinv,    d_sinv);
    cudaGetSymbolAddress((void**)&xcs,     d_xcs);
    cudaGetSymbolAddress((void**)&specW,   d_specW);
    cudaGetSymbolAddress((void**)&f0,      d_f0);
    cudaGetSymbolAddress((void**)&wcat,    d_wcat);
    cudaGetSymbolAddress((void**)&wtc,     d_wtc);
    cudaGetSymbolAddress((void**)&wts,     d_wts);
    cudaGetSymbolAddress((void**)&fc1wt,   d_fc1wt);
    cudaGetSymbolAddress((void**)&count,   d_count);
    cudaGetSymbolAddress((void**)&cursor,  d_cursor);
    cudaGetSymbolAddress((void**)&offsets, d_offsets);
    cudaGetSymbolAddress((void**)&esrc,    d_esrc);
    cudaGetSymbolAddress((void**)&ew3,     d_ew3);

    // CSR build (edges constant across layers)
    cudaMemsetAsync(count, 0, BB * NN * sizeof(int), 0);
    hist_kernel<<<(BB * EE + 255) / 256, 256>>>(edges, count);
    scan_kernel<<<BB, 1024>>>(count, offsets);
    cudaMemsetAsync(cursor, 0, BB * NN * sizeof(int), 0);
    fill_kernel<<<(BB * EE + 255) / 256, 256>>>(edges, egw, offsets, cursor, esrc, ew3);

    basis_kernel<<<(BB * NN + 127) / 128, 128>>>(nodes, modes, latent, cosv, sinv);
    fc0_kernel<<<(BB * NN * CC + 255) / 256, 256>>>(x, fc0_w, fc0_b, hA);
    transpose_fc1_kernel<<<(CC * CC + 255) / 256, 256>>>(fc1_w, fc1wt);

    float* hin = hA;
    float* hout = hB;
    for (int l = 0; l < 3; l++) {
        transpose_w_kernel<<<(CC * CC * NM + 255) / 256, 256>>>(
            swc + (size_t)l * CC * CC * NM, wtc);
        transpose_w_kernel<<<(CC * CC * NM + 255) / 256, 256>>>(
            sws + (size_t)l * CC * CC * NM, wts);
        cudaMemsetAsync(xcs, 0, (size_t)BB * 65 * CC * sizeof(float), 0);
        forward_kernel<<<dim3(NN / FCHUNK, BB), 128>>>(hin, cosv, sinv, nw, xcs);
        modemix_kernel<<<dim3(BB, 33), 128>>>(
            xcs, wtc, wts, sw0 + (size_t)l * CC * CC, specW, f0);
        wcat_kernel<<<(512 * CC + 255) / 256, 256>>>(
            ww + (size_t)l * CC * CC, gw + (size_t)l * CC * 384, wcat);
        gather_kernel<<<dim3(NN, BB), 128>>>(hin, offsets, esrc, ew3, g);
        combine_kernel<<<dim3((NN + 127) / 128, BB), 256>>>(
            hin, g, cosv, sinv, wcat, specW, f0,
            wb + l * CC, gb + l * CC, hout, (l < 2) ? 1 : 0);
        float* t = hin; hin = hout; hout = t;
    }
    final_gemm<<<(BB * NN) / 128, 256>>>(hin, fc1wt, fc1_b, fc2_w, fc2_b, out);
}

// round 3
// speedup vs baseline: 3.1789x; 1.0572x over previous
#include <cuda_runtime.h>
#include <math.h>
#include <stdint.h>

#define BB 4
#define NN 20000
#define EE 100000
#define CC 128
#define NM 32

// ---------------- scratch (static device globals; no allocation) -------------
__device__ float d_hA[BB * NN * CC];
__device__ float d_hB[BB * NN * CC];
__device__ float d_g[(size_t)BB * NN * 384];
__device__ float d_cosv[BB * NN * NM];
__device__ float d_sinv[BB * NN * NM];
__device__ float d_xcs[BB * 65 * CC];
__device__ float d_specW[BB * 64 * CC];
__device__ float d_f0[BB * CC];
__device__ float d_wcat[512 * CC];
__device__ float d_wtc[NM * CC * CC];     // [k][c][o]
__device__ float d_wts[NM * CC * CC];     // [k][c][o]
__device__ float d_fc1wt[CC * CC];        // [c][j]
// CSR scratch
__device__ int   d_count[BB * NN];
__device__ int   d_cursor[BB * NN];
__device__ int   d_offsets[BB * (NN + 1)];
__device__ int   d_esrc[BB * EE];
__device__ float d_ew3[(size_t)BB * EE * 3];

__device__ __forceinline__ float gelu_f(float v) {
    return 0.5f * v * (1.f + erff(v * 0.70710678118654752f));
}

__device__ __forceinline__ float to_tf32(float x) {
    uint32_t u;
    asm("cvt.rna.tf32.f32 %0, %1;" : "=r"(u) : "f"(x));
    return __uint_as_float(u);
}

__device__ __forceinline__ void mma_tf32(float* d, const uint32_t* a, const uint32_t* b) {
    asm volatile(
        "mma.sync.aligned.m16n8k8.row.col.f32.tf32.tf32.f32 "
        "{%0,%1,%2,%3}, {%4,%5,%6,%7}, {%8,%9}, {%0,%1,%2,%3};"
        : "+f"(d[0]), "+f"(d[1]), "+f"(d[2]), "+f"(d[3])
        : "r"(a[0]), "r"(a[1]), "r"(a[2]), "r"(a[3]), "r"(b[0]), "r"(b[1]));
}

// ---------------- basis ------------------------------------------------------
__global__ void basis_kernel(const float* __restrict__ nodes,
                             const float* __restrict__ modes,
                             const float* __restrict__ latent,
                             float* __restrict__ cosv, float* __restrict__ sinv) {
    int idx = blockIdx.x * blockDim.x + threadIdx.x;
    if (idx >= BB * NN) return;
    float il0 = 0.5f + 1.5f / (1.f + expf(-latent[0]));
    float il1 = 0.5f + 1.5f / (1.f + expf(-latent[1]));
    float il2 = 0.5f + 1.5f / (1.f + expf(-latent[2]));
    float n0 = nodes[idx * 3 + 0];
    float n1 = nodes[idx * 3 + 1];
    float n2 = nodes[idx * 3 + 2];
    #pragma unroll
    for (int k = 0; k < NM; k++) {
        float t = n0 * modes[k * 3 + 0] * il0
                + n1 * modes[k * 3 + 1] * il1
                + n2 * modes[k * 3 + 2] * il2;
        float s, c;
        sincosf(t, &s, &c);
        cosv[idx * NM + k] = c;
        sinv[idx * NM + k] = s;
    }
}

// ---------------- fc0 --------------------------------------------------------
__global__ void fc0_kernel(const float* __restrict__ x, const float* __restrict__ w,
                           const float* __restrict__ bias, float* __restrict__ h) {
    int idx = blockIdx.x * blockDim.x + threadIdx.x;
    if (idx >= BB * NN * CC) return;
    int c = idx & 127;
    int node = idx >> 7;
    h[idx] = bias[c] + x[node * 3 + 0] * w[c * 3 + 0]
                     + x[node * 3 + 1] * w[c * 3 + 1]
                     + x[node * 3 + 2] * w[c * 3 + 2];
}

// ---------------- CSR build --------------------------------------------------
__global__ void hist_kernel(const int* __restrict__ edges, int* __restrict__ count) {
    int idx = blockIdx.x * blockDim.x + threadIdx.x;
    if (idx >= BB * EE) return;
    int b = idx / EE;
    int tgt = edges[idx * 2 + 0];
    atomicAdd(&count[b * NN + tgt], 1);
}

__global__ void scan_kernel(const int* __restrict__ count, int* __restrict__ offsets) {
    int b = blockIdx.x;
    int t = threadIdx.x;              // 1024
    __shared__ int sums[1024];
    const int CH = 20;
    int base = t * CH;
    int s = 0;
    for (int i = 0; i < CH; i++) {
        int n = base + i;
        if (n < NN) s += count[b * NN + n];
    }
    sums[t] = s;
    __syncthreads();
    for (int off = 1; off < 1024; off <<= 1) {
        int v = (t >= off) ? sums[t - off] : 0;
        __syncthreads();
        sums[t] += v;
        __syncthreads();
    }
    int run = (t == 0) ? 0 : sums[t - 1];
    for (int i = 0; i < CH; i++) {
        int n = base + i;
        if (n < NN) {
            offsets[b * (NN + 1) + n] = run;
            run += count[b * NN + n];
        }
    }
    if (t == 1023) offsets[b * (NN + 1) + NN] = sums[1023];
}

__global__ void fill_kernel(const int* __restrict__ edges, const float* __restrict__ egw,
                            const int* __restrict__ offsets, int* __restrict__ cursor,
                            int* __restrict__ esrc, float* __restrict__ ew3) {
    int idx = blockIdx.x * blockDim.x + threadIdx.x;
    if (idx >= BB * EE) return;
    int b = idx / EE;
    int tgt = edges[idx * 2 + 0];
    int src = edges[idx * 2 + 1];
    int pos = offsets[b * (NN + 1) + tgt] + atomicAdd(&cursor[b * NN + tgt], 1);
    int gp = b * EE + pos;
    esrc[gp] = src;
    ew3[(size_t)gp * 3 + 0] = egw[(size_t)idx * 3 + 0];
    ew3[(size_t)gp * 3 + 1] = egw[(size_t)idx * 3 + 1];
    ew3[(size_t)gp * 3 + 2] = egw[(size_t)idx * 3 + 2];
}

// ---------------- gradient gather (no atomics, 16 nodes/block) ---------------
#define NPB 16
__global__ void gather_kernel(const float* __restrict__ h,
                              const int* __restrict__ offsets,
                              const int* __restrict__ esrc,
                              const float* __restrict__ ew3,
                              float* __restrict__ g) {
    int b = blockIdx.y;
    int c = threadIdx.x;   // 128
    int nb = blockIdx.x * NPB;
    for (int nn = 0; nn < NPB; nn++) {
        int n = nb + nn;
        int o0 = offsets[b * (NN + 1) + n];
        int o1 = offsets[b * (NN + 1) + n + 1];
        float ht = h[(b * NN + n) * CC + c];
        float a0 = 0.f, a1 = 0.f, a2 = 0.f;
        for (int j = o0; j < o1; j++) {
            int src = esrc[b * EE + j];
            float hs = h[(b * NN + src) * CC + c];
            float d = hs - ht;
            a0 += ew3[(size_t)(b * EE + j) * 3 + 0] * d;
            a1 += ew3[(size_t)(b * EE + j) * 3 + 1] * d;
            a2 += ew3[(size_t)(b * EE + j) * 3 + 2] * d;
        }
        size_t gb_ = (size_t)(b * NN + n) * 384 + c * 3;
        g[gb_ + 0] = a0;
        g[gb_ + 1] = a1;
        g[gb_ + 2] = a2;
    }
}

// ---------------- forward spectral transform (512 thr, 4-node parallel) ------
#define FCHUNK 100
__global__ void __launch_bounds__(512)
forward_kernel(const float* __restrict__ h,
               const float* __restrict__ cosv,
               const float* __restrict__ sinv,
               const float* __restrict__ nw,
               float* __restrict__ xcs) {
    int b = blockIdx.y;
    int tid = threadIdx.x;           // 512
    int sub = tid >> 7;              // 0..3
    int c = tid & 127;
    int n0 = blockIdx.x * FCHUNK;
    float acc[65];
    #pragma unroll
    for (int r = 0; r < 65; r++) acc[r] = 0.f;
    __shared__ float sb[4][65];
    __shared__ float red[4][16][128];
    for (int base = n0; base < n0 + FCHUNK; base += 4) {
        for (int l = tid; l < 4 * 65; l += 512) {
            int i = l / 65;
            int r = l - i * 65;
            int node = base + i;
            float w = nw[b * NN + node];
            float v;
            if (r < 32)      v = w * cosv[(b * NN + node) * NM + r];
            else if (r < 64) v = w * sinv[(b * NN + node) * NM + (r - 32)];
            else             v = w;
            sb[i][r] = v;
        }
        __syncthreads();
        int node = base + sub;
        float hv = h[(b * NN + node) * CC + c];
        #pragma unroll
        for (int r = 0; r < 65; r++) acc[r] += hv * sb[sub][r];
        __syncthreads();
    }
    // cross-sub reduction, 16 rows at a time
    for (int r0 = 0; r0 < 65; r0 += 16) {
        int nr = min(16, 65 - r0);
        for (int rr = 0; rr < nr; rr++) red[sub][rr][c] = acc[r0 + rr];
        __syncthreads();
        for (int p = tid; p < nr * 128; p += 512) {
            int r = p >> 7, cc = p & 127;
            float s = red[0][r][cc] + red[1][r][cc] + red[2][r][cc] + red[3][r][cc];
            atomicAdd(&xcs[(b * 65 + r0 + r) * CC + cc], s);
        }
        __syncthreads();
    }
}

// ---------------- weight transposes ------------------------------------------
__global__ void transpose_w_kernel(const float* __restrict__ src, float* __restrict__ dst) {
    int idx = blockIdx.x * blockDim.x + threadIdx.x;
    if (idx >= CC * CC * NM) return;
    int k = idx & 31;
    int co = idx >> 5;
    int o = co & 127;
    int c = co >> 7;
    dst[(k * CC + c) * CC + o] = src[idx];
}

__global__ void transpose_fc1_kernel(const float* __restrict__ src, float* __restrict__ dst) {
    int idx = blockIdx.x * blockDim.x + threadIdx.x;
    if (idx >= CC * CC) return;
    int c = idx & 127;
    int j = idx >> 7;
    dst[c * CC + j] = src[idx];
}

// ---------------- mode mixing ------------------------------------------------
__global__ void modemix_kernel(const float* __restrict__ xcs,
                               const float* __restrict__ wtc,
                               const float* __restrict__ wts,
                               const float* __restrict__ sw0_l,
                               float* __restrict__ specW, float* __restrict__ f0) {
    int b = blockIdx.x;
    int k = blockIdx.y;
    int o = threadIdx.x;
    __shared__ float xc_s[CC], xs_s[CC];
    if (k < 32) {
        xc_s[o] = xcs[(b * 65 + k) * CC + o];
        xs_s[o] = xcs[(b * 65 + 32 + k) * CC + o];
        __syncthreads();
        float fc = 0.f, fs = 0.f;
        #pragma unroll 4
        for (int c = 0; c < CC; c++) {
            float wc = wtc[(k * CC + c) * CC + o];
            float ws = wts[(k * CC + c) * CC + o];
            float a = xc_s[c], s2 = xs_s[c];
            fc += a * wc - s2 * ws;
            fs += s2 * wc + a * ws;
        }
        specW[(b * 64 + k) * CC + o]      =  2.f * fc;
        specW[(b * 64 + 32 + k) * CC + o] = -2.f * fs;
    } else {
        xc_s[o] = xcs[(b * 65 + 64) * CC + o];
        __syncthreads();
        float f = 0.f;
        #pragma unroll 4
        for (int c = 0; c < CC; c++) f += xc_s[c] * sw0_l[c * CC + o];
        f0[b * CC + o] = f;
    }
}

// ---------------- concat weight transpose ------------------------------------
__global__ void wcat_kernel(const float* __restrict__ ww_l,
                            const float* __restrict__ gw_l,
                            float* __restrict__ wcat) {
    int idx = blockIdx.x * blockDim.x + threadIdx.x;
    if (idx >= 512 * CC) return;
    int k = idx >> 7, o = idx & 127;
    wcat[idx] = (k < 128) ? ww_l[o * CC + k] : gw_l[o * 384 + (k - 128)];
}

// ---------------- fused combine GEMM — tf32 tensor-core ----------------------
// 128x128 tile, K=576, 8 warps (4M x 2N), mma m16n8k8, double-buffered smem.
#define AS_STRIDE 20
#define WS_STRIDE 132
__global__ void __launch_bounds__(256, 2)
combine_mma(const float* __restrict__ h, const float* __restrict__ g,
            const float* __restrict__ cosv, const float* __restrict__ sinv,
            const float* __restrict__ wcat, const float* __restrict__ specW,
            const float* __restrict__ f0, const float* __restrict__ wb,
            const float* __restrict__ gb, float* __restrict__ hout,
            int gelu_flag) {
    int b = blockIdx.y;
    int n0 = blockIdx.x * 128;
    int tid = threadIdx.x;
    int warp = tid >> 5, lane = tid & 31;
    int grp = lane >> 2, tig = lane & 3;
    int wm = (warp >> 1) * 32;
    int wn = (warp & 1) * 64;

    __shared__ float As[2][128][AS_STRIDE];
    __shared__ float Ws[2][16][WS_STRIDE];
    __shared__ float bias_s[128];
    if (tid < 128) bias_s[tid] = wb[tid] + gb[tid] + f0[b * CC + tid];

    float acc[2][8][4];
    #pragma unroll
    for (int i = 0; i < 2; i++)
        #pragma unroll
        for (int j = 0; j < 8; j++)
            #pragma unroll
            for (int q = 0; q < 4; q++) acc[i][j][q] = 0.f;

    float a_reg[8], b_reg[8];

    // --- tile loaders (into regs, tf32-rounded) ---
    auto load_regs = [&](int kt) {
        int kbase = kt * 16;
        #pragma unroll
        for (int r = 0; r < 8; r++) {
            int l = tid + r * 256;
            int m = l >> 4, kk = l & 15;
            int n = n0 + m;
            int k = kbase + kk;
            float v = 0.f;
            if (n < NN) {
                int base = b * NN + n;
                if (k < 128)      v = h[base * 128 + k];
                else if (k < 512) v = g[(size_t)base * 384 + (k - 128)];
                else if (k < 544) v = cosv[base * 32 + (k - 512)];
                else              v = sinv[base * 32 + (k - 544)];
            }
            a_reg[r] = to_tf32(v);
        }
        #pragma unroll
        for (int r = 0; r < 8; r++) {
            int l = tid + r * 256;
            int kk = l >> 7, o = l & 127;
            int k = kbase + kk;
            float v = (k < 512) ? wcat[k * 128 + o]
                                : specW[(b * 64 + (k - 512)) * 128 + o];
            b_reg[r] = to_tf32(v);
        }
    };
    auto store_regs = [&](int buf) {
        #pragma unroll
        for (int r = 0; r < 8; r++) {
            int l = tid + r * 256;
            As[buf][l >> 4][l & 15] = a_reg[r];
        }
        #pragma unroll
        for (int r = 0; r < 8; r++) {
            int l = tid + r * 256;
            Ws[buf][l >> 7][l & 127] = b_reg[r];
        }
    };

    load_regs(0);
    store_regs(0);
    __syncthreads();

    for (int kt = 0; kt < 36; kt++) {
        int cur = kt & 1;
        if (kt < 35) load_regs(kt + 1);
        #pragma unroll
        for (int k8 = 0; k8 < 2; k8++) {
            int k0 = k8 * 8;
            uint32_t afr[2][4];
            #pragma unroll
            for (int i = 0; i < 2; i++) {
                int r0 = wm + i * 16 + grp;
                afr[i][0] = __float_as_uint(As[cur][r0][k0 + tig]);
                afr[i][1] = __float_as_uint(As[cur][r0 + 8][k0 + tig]);
                afr[i][2] = __float_as_uint(As[cur][r0][k0 + tig + 4]);
                afr[i][3] = __float_as_uint(As[cur][r0 + 8][k0 + tig + 4]);
            }
            uint32_t bfr[8][2];
            #pragma unroll
            for (int j = 0; j < 8; j++) {
                int o = wn + j * 8 + grp;
                bfr[j][0] = __float_as_uint(Ws[cur][k0 + tig][o]);
                bfr[j][1] = __float_as_uint(Ws[cur][k0 + tig + 4][o]);
            }
            #pragma unroll
            for (int i = 0; i < 2; i++)
                #pragma unroll
                for (int j = 0; j < 8; j++)
                    mma_tf32(acc[i][j], afr[i], bfr[j]);
        }
        if (kt < 35) store_regs((kt + 1) & 1);
        __syncthreads();
    }

    // --- epilogue ---
    #pragma unroll
    for (int i = 0; i < 2; i++) {
        int row0 = wm + i * 16 + grp;
        #pragma unroll
        for (int j = 0; j < 8; j++) {
            int col = wn + j * 8 + tig * 2;
            #pragma unroll
            for (int half = 0; half < 2; half++) {
                int row = row0 + half * 8;
                int n = n0 + row;
                if (n < NN) {
                    float v0 = acc[i][j][half * 2 + 0] + bias_s[col];
                    float v1 = acc[i][j][half * 2 + 1] + bias_s[col + 1];
                    if (gelu_flag) { v0 = gelu_f(v0); v1 = gelu_f(v1); }
                    hout[(b * NN + n) * CC + col] = v0;
                    hout[(b * NN + n) * CC + col + 1] = v1;
                }
            }
        }
    }
}

// ---------------- final fused MLP GEMM (fp32) --------------------------------
__global__ void __launch_bounds__(256, 2)
final_gemm(const float* __restrict__ h, const float* __restrict__ fc1wt,
           const float* __restrict__ fc1_b, const float* __restrict__ fc2_w,
           const float* __restrict__ fc2_b, float* __restrict__ out) {
    int m0 = blockIdx.x * 128;
    int tid = threadIdx.x;
    int tx = tid & 15, ty = tid >> 4;
    __shared__ float As[128][17];
    __shared__ float Ws[16][128];
    float acc[8][8];
    #pragma unroll
    for (int i = 0; i < 8; i++)
        #pragma unroll
        for (int j = 0; j < 8; j++) acc[i][j] = 0.f;

    for (int kt = 0; kt < 8; kt++) {
        int kbase = kt * 16;
        #pragma unroll
        for (int r = 0; r < 8; r++) {
            int l = tid + r * 256;
            int nl = l >> 4, kk = l & 15;
            As[nl][kk] = h[(m0 + nl) * CC + kbase + kk];
        }
        #pragma unroll
        for (int r = 0; r < 8; r++) {
            int l = tid + r * 256;
            int kk = l >> 7, o = l & 127;
            Ws[kk][o] = fc1wt[(kbase + kk) * CC + o];
        }
        __syncthreads();
        #pragma unroll
        for (int kk = 0; kk < 16; kk++) {
            float a[8];
            #pragma unroll
            for (int i = 0; i < 8; i++) a[i] = As[ty + 16 * i][kk];
            float4 w0 = *(const float4*)&Ws[kk][tx * 4];
            float4 w1 = *(const float4*)&Ws[kk][64 + tx * 4];
            float w[8] = {w0.x, w0.y, w0.z, w0.w, w1.x, w1.y, w1.z, w1.w};
            #pragma unroll
            for (int i = 0; i < 8; i++)
                #pragma unroll
                for (int j = 0; j < 8; j++) acc[i][j] += a[i] * w[j];
        }
        __syncthreads();
    }
    float part[8];
    #pragma unroll
    for (int i = 0; i < 8; i++) {
        float p = 0.f;
        #pragma unroll
        for (int j = 0; j < 8; j++) {
            int o = (j < 4) ? (tx * 4 + j) : (64 + tx * 4 + (j - 4));
            float v = acc[i][j] + fc1_b[o];
            v = gelu_f(v);
            p += v * fc2_w[o];
        }
        part[i] = p;
    }
    __syncthreads();
    #pragma unroll
    for (int i = 0; i < 8; i++) As[ty + 16 * i][tx] = part[i];
    __syncthreads();
    if (tid < 128) {
        float s = 0.f;
        #pragma unroll
        for (int t = 0; t < 16; t++) s += As[tid][t];
        out[m0 + tid] = s + fc2_b[0];
    }
}

// ---------------- launcher ----------------------------------------------------
extern "C" void kernel_launch(void* const* d_in, const int* in_sizes, int n_in,
                              void* d_out, int out_size) {
    const float* x      = (const float*)d_in[0];
    const float* nodes  = (const float*)d_in[2];
    const float* nw     = (const float*)d_in[3];
    const int*   edges  = (const int*)  d_in[4];
    const float* egw    = (const float*)d_in[5];
    const float* modes  = (const float*)d_in[6];
    const float* latent = (const float*)d_in[7];
    const float* fc0_w  = (const float*)d_in[8];
    const float* fc0_b  = (const float*)d_in[9];
    const float* swc    = (const float*)d_in[10];
    const float* sws    = (const float*)d_in[11];
    const float* sw0    = (const float*)d_in[12];
    const float* ww     = (const float*)d_in[13];
    const float* wb     = (const float*)d_in[14];
    const float* gw     = (const float*)d_in[15];
    const float* gb     = (const float*)d_in[16];
    const float* fc1_w  = (const float*)d_in[17];
    const float* fc1_b  = (const float*)d_in[18];
    const float* fc2_w  = (const float*)d_in[19];
    const float* fc2_b  = (const float*)d_in[20];
    float* out = (float*)d_out;

    float *hA, *hB, *g, *cosv, *sinv, *xcs, *specW, *f0, *wcat, *wtc, *wts, *fc1wt, *ew3;
    int *count, *cursor, *offsets, *esrc;
    cudaGetSymbolAddress((void**)&hA,      d_hA);
    cudaGetSymbolAddress((void**)&hB,      d_hB);
    cudaGetSymbolAddress((void**)&g,       d_g);
    cudaGetSymbolAddress((void**)&cosv,    d_cosv);
    cudaGetSymbolAddress((void**)&sinv,    d_sinv);
    cudaGetSymbolAddress((void**)&xcs,     d_xcs);
    cudaGetSymbolAddress((void**)&specW,   d_specW);
    cudaGetSymbolAddress((void**)&f0,      d_f0);
    cudaGetSymbolAddress((void**)&wcat,    d_wcat);
    cudaGetSymbolAddress((void**)&wtc,     d_wtc);
    cudaGetSymbolAddress((void**)&wts,     d_wts);
    cudaGetSymbolAddress((void**)&fc1wt,   d_fc1wt);
    cudaGetSymbolAddress((void**)&count,   d_count);
    cudaGetSymbolAddress((void**)&cursor,  d_cursor);
    cudaGetSymbolAddress((void**)&offsets, d_offsets);
    cudaGetSymbolAddress((void**)&esrc,    d_esrc);
    cudaGetSymbolAddress((void**)&ew3,     d_ew3);

    // CSR build (edges constant across layers)
    cudaMemsetAsync(count, 0, BB * NN * sizeof(int), 0);
    hist_kernel<<<(BB * EE + 255) / 256, 256>>>(edges, count);
    scan_kernel<<<BB, 1024>>>(count, offsets);
    cudaMemsetAsync(cursor, 0, BB * NN * sizeof(int), 0);
    fill_kernel<<<(BB * EE + 255) / 256, 256>>>(edges, egw, offsets, cursor, esrc, ew3);

    basis_kernel<<<(BB * NN + 127) / 128, 128>>>(nodes, modes, latent, cosv, sinv);
    fc0_kernel<<<(BB * NN * CC + 255) / 256, 256>>>(x, fc0_w, fc0_b, hA);
    transpose_fc1_kernel<<<(CC * CC + 255) / 256, 256>>>(fc1_w, fc1wt);

    float* hin = hA;
    float* hout = hB;
    for (int l = 0; l < 3; l++) {
        transpose_w_kernel<<<(CC * CC * NM + 255) / 256, 256>>>(
            swc + (size_t)l * CC * CC * NM, wtc);
        transpose_w_kernel<<<(CC * CC * NM + 255) / 256, 256>>>(
            sws + (size_t)l * CC * CC * NM, wts);
        cudaMemsetAsync(xcs, 0, (size_t)BB * 65 * CC * sizeof(float), 0);
        forward_kernel<<<dim3(NN / FCHUNK, BB), 512>>>(hin, cosv, sinv, nw, xcs);
        modemix_kernel<<<dim3(BB, 33), 128>>>(
            xcs, wtc, wts, sw0 + (size_t)l * CC * CC, specW, f0);
        wcat_kernel<<<(512 * CC + 255) / 256, 256>>>(
            ww + (size_t)l * CC * CC, gw + (size_t)l * CC * 384, wcat);
        gather_kernel<<<dim3(NN / NPB, BB), 128>>>(hin, offsets, esrc, ew3, g);
        combine_mma<<<dim3((NN + 127) / 128, BB), 256>>>(
            hin, g, cosv, sinv, wcat, specW, f0,
            wb + l * CC, gb + l * CC, hout, (l < 2) ? 1 : 0);
        float* t = hin; hin = hout; hout = t;
    }
    final_gemm<<<(BB * NN) / 128, 256>>>(hin, fc1wt, fc1_b, fc2_w, fc2_b, out);
}

// round 4
// speedup vs baseline: 4.9658x; 1.5621x over previous
#include <cuda_runtime.h>
#include <math.h>
#include <stdint.h>

#define BB 4
#define NN 20000
#define EE 100000
#define CC 128
#define NM 32

// ---------------- scratch (static device globals; no allocation) -------------
__device__ float d_hA[BB * NN * CC];
__device__ float d_hB[BB * NN * CC];
__device__ float d_g[(size_t)BB * NN * 384];
__device__ float d_cosv[BB * NN * NM];
__device__ float d_sinv[BB * NN * NM];
__device__ float d_xcs[BB * 65 * CC];
__device__ float d_specW[BB * 64 * CC];
__device__ float d_f0[BB * CC];
__device__ float d_wcat[512 * CC];
__device__ float d_wtc[NM * CC * CC];     // [k][c][o]
__device__ float d_wts[NM * CC * CC];     // [k][c][o]
__device__ float d_fc1wt[CC * CC];        // [c][j]
// CSR scratch
__device__ int   d_count[BB * NN];
__device__ int   d_cursor[BB * NN];
__device__ int   d_offsets[BB * (NN + 1)];
__device__ int   d_esrc[BB * EE];
__device__ float d_ew3[(size_t)BB * EE * 3];

__device__ __forceinline__ float gelu_f(float v) {
    return 0.5f * v * (1.f + erff(v * 0.70710678118654752f));
}

__device__ __forceinline__ float to_tf32(float x) {
    uint32_t u;
    asm("cvt.rna.tf32.f32 %0, %1;" : "=r"(u) : "f"(x));
    return __uint_as_float(u);
}

__device__ __forceinline__ void mma_tf32(float* d, const uint32_t* a, const uint32_t* b) {
    asm volatile(
        "mma.sync.aligned.m16n8k8.row.col.f32.tf32.tf32.f32 "
        "{%0,%1,%2,%3}, {%4,%5,%6,%7}, {%8,%9}, {%0,%1,%2,%3};"
        : "+f"(d[0]), "+f"(d[1]), "+f"(d[2]), "+f"(d[3])
        : "r"(a[0]), "r"(a[1]), "r"(a[2]), "r"(a[3]), "r"(b[0]), "r"(b[1]));
}

__device__ __forceinline__ void cp16(void* smem_dst, const void* gsrc, int src_bytes) {
    uint32_t d = (uint32_t)__cvta_generic_to_shared(smem_dst);
    asm volatile("cp.async.cg.shared.global [%0], [%1], 16, %2;"
                 :: "r"(d), "l"(gsrc), "r"(src_bytes));
}
#define CP_COMMIT asm volatile("cp.async.commit_group;")
#define CP_WAIT0  asm volatile("cp.async.wait_group 0;")

// ---------------- basis (tf32-rounded outputs) -------------------------------
__global__ void basis_kernel(const float* __restrict__ nodes,
                             const float* __restrict__ modes,
                             const float* __restrict__ latent,
                             float* __restrict__ cosv, float* __restrict__ sinv) {
    int idx = blockIdx.x * blockDim.x + threadIdx.x;
    if (idx >= BB * NN) return;
    float il0 = 0.5f + 1.5f / (1.f + expf(-latent[0]));
    float il1 = 0.5f + 1.5f / (1.f + expf(-latent[1]));
    float il2 = 0.5f + 1.5f / (1.f + expf(-latent[2]));
    float n0 = nodes[idx * 3 + 0];
    float n1 = nodes[idx * 3 + 1];
    float n2 = nodes[idx * 3 + 2];
    #pragma unroll
    for (int k = 0; k < NM; k++) {
        float t = n0 * modes[k * 3 + 0] * il0
                + n1 * modes[k * 3 + 1] * il1
                + n2 * modes[k * 3 + 2] * il2;
        float s, c;
        sincosf(t, &s, &c);
        cosv[idx * NM + k] = to_tf32(c);
        sinv[idx * NM + k] = to_tf32(s);
    }
}

// ---------------- fc0 (tf32-rounded) -----------------------------------------
__global__ void fc0_kernel(const float* __restrict__ x, const float* __restrict__ w,
                           const float* __restrict__ bias, float* __restrict__ h) {
    int idx = blockIdx.x * blockDim.x + threadIdx.x;
    if (idx >= BB * NN * CC) return;
    int c = idx & 127;
    int node = idx >> 7;
    float v = bias[c] + x[node * 3 + 0] * w[c * 3 + 0]
                      + x[node * 3 + 1] * w[c * 3 + 1]
                      + x[node * 3 + 2] * w[c * 3 + 2];
    h[idx] = to_tf32(v);
}

// ---------------- CSR build --------------------------------------------------
__global__ void hist_kernel(const int* __restrict__ edges, int* __restrict__ count) {
    int idx = blockIdx.x * blockDim.x + threadIdx.x;
    if (idx >= BB * EE) return;
    int b = idx / EE;
    int tgt = edges[idx * 2 + 0];
    atomicAdd(&count[b * NN + tgt], 1);
}

__global__ void scan_kernel(const int* __restrict__ count, int* __restrict__ offsets) {
    int b = blockIdx.x;
    int t = threadIdx.x;              // 1024
    __shared__ int sums[1024];
    const int CH = 20;
    int base = t * CH;
    int s = 0;
    for (int i = 0; i < CH; i++) {
        int n = base + i;
        if (n < NN) s += count[b * NN + n];
    }
    sums[t] = s;
    __syncthreads();
    for (int off = 1; off < 1024; off <<= 1) {
        int v = (t >= off) ? sums[t - off] : 0;
        __syncthreads();
        sums[t] += v;
        __syncthreads();
    }
    int run = (t == 0) ? 0 : sums[t - 1];
    for (int i = 0; i < CH; i++) {
        int n = base + i;
        if (n < NN) {
            offsets[b * (NN + 1) + n] = run;
            run += count[b * NN + n];
        }
    }
    if (t == 1023) offsets[b * (NN + 1) + NN] = sums[1023];
}

__global__ void fill_kernel(const int* __restrict__ edges, const float* __restrict__ egw,
                            const int* __restrict__ offsets, int* __restrict__ cursor,
                            int* __restrict__ esrc, float* __restrict__ ew3) {
    int idx = blockIdx.x * blockDim.x + threadIdx.x;
    if (idx >= BB * EE) return;
    int b = idx / EE;
    int tgt = edges[idx * 2 + 0];
    int src = edges[idx * 2 + 1];
    int pos = offsets[b * (NN + 1) + tgt] + atomicAdd(&cursor[b * NN + tgt], 1);
    int gp = b * EE + pos;
    esrc[gp] = src;
    ew3[(size_t)gp * 3 + 0] = egw[(size_t)idx * 3 + 0];
    ew3[(size_t)gp * 3 + 1] = egw[(size_t)idx * 3 + 1];
    ew3[(size_t)gp * 3 + 2] = egw[(size_t)idx * 3 + 2];
}

// ---------------- gradient gather (tf32-rounded out) -------------------------
#define NPB 4
__global__ void gather_kernel(const float* __restrict__ h,
                              const int* __restrict__ offsets,
                              const int* __restrict__ esrc,
                              const float* __restrict__ ew3,
                              float* __restrict__ g) {
    int b = blockIdx.y;
    int c = threadIdx.x;   // 128
    int nb = blockIdx.x * NPB;
    for (int nn = 0; nn < NPB; nn++) {
        int n = nb + nn;
        int o0 = offsets[b * (NN + 1) + n];
        int o1 = offsets[b * (NN + 1) + n + 1];
        float ht = h[(b * NN + n) * CC + c];
        float a0 = 0.f, a1 = 0.f, a2 = 0.f;
        for (int j = o0; j < o1; j++) {
            int src = esrc[b * EE + j];
            float hs = h[(b * NN + src) * CC + c];
            float d = hs - ht;
            a0 += ew3[(size_t)(b * EE + j) * 3 + 0] * d;
            a1 += ew3[(size_t)(b * EE + j) * 3 + 1] * d;
            a2 += ew3[(size_t)(b * EE + j) * 3 + 2] * d;
        }
        size_t gb_ = (size_t)(b * NN + n) * 384 + c * 3;
        g[gb_ + 0] = to_tf32(a0);
        g[gb_ + 1] = to_tf32(a1);
        g[gb_ + 2] = to_tf32(a2);
    }
}

// ---------------- forward spectral transform ---------------------------------
#define FCHUNK 100
__global__ void __launch_bounds__(512)
forward_kernel(const float* __restrict__ h,
               const float* __restrict__ cosv,
               const float* __restrict__ sinv,
               const float* __restrict__ nw,
               float* __restrict__ xcs) {
    int b = blockIdx.y;
    int tid = threadIdx.x;           // 512
    int sub = tid >> 7;              // 0..3
    int c = tid & 127;
    int n0 = blockIdx.x * FCHUNK;
    float acc[65];
    #pragma unroll
    for (int r = 0; r < 65; r++) acc[r] = 0.f;
    __shared__ float sb[4][65];
    __shared__ float red[4][16][128];
    for (int base = n0; base < n0 + FCHUNK; base += 4) {
        for (int l = tid; l < 4 * 65; l += 512) {
            int i = l / 65;
            int r = l - i * 65;
            int node = base + i;
            float w = nw[b * NN + node];
            float v;
            if (r < 32)      v = w * cosv[(b * NN + node) * NM + r];
            else if (r < 64) v = w * sinv[(b * NN + node) * NM + (r - 32)];
            else             v = w;
            sb[i][r] = v;
        }
        __syncthreads();
        int node = base + sub;
        float hv = h[(b * NN + node) * CC + c];
        #pragma unroll
        for (int r = 0; r < 65; r++) acc[r] += hv * sb[sub][r];
        __syncthreads();
    }
    for (int r0 = 0; r0 < 65; r0 += 16) {
        int nr = min(16, 65 - r0);
        for (int rr = 0; rr < nr; rr++) red[sub][rr][c] = acc[r0 + rr];
        __syncthreads();
        for (int p = tid; p < nr * 128; p += 512) {
            int r = p >> 7, cc = p & 127;
            float s = red[0][r][cc] + red[1][r][cc] + red[2][r][cc] + red[3][r][cc];
            atomicAdd(&xcs[(b * 65 + r0 + r) * CC + cc], s);
        }
        __syncthreads();
    }
}

// ---------------- generic tiled transpose: src[R][C] -> dst[C][R] ------------
__global__ void transpose_kernel(const float* __restrict__ src, float* __restrict__ dst,
                                 int R, int C, int do_round) {
    __shared__ float tile[32][33];
    int c0 = blockIdx.x * 32;
    int r0 = blockIdx.y * 32;
    int tx = threadIdx.x, ty = threadIdx.y;   // 32 x 8
    #pragma unroll
    for (int i = 0; i < 4; i++) {
        int r = r0 + ty + i * 8;
        int c = c0 + tx;
        if (r < R && c < C) tile[ty + i * 8][tx] = src[r * C + c];
    }
    __syncthreads();
    #pragma unroll
    for (int i = 0; i < 4; i++) {
        int c = c0 + ty + i * 8;
        int r = r0 + tx;
        if (r < R && c < C) {
            float v = tile[tx][ty + i * 8];
            dst[c * R + r] = do_round ? to_tf32(v) : v;
        }
    }
}

// ---------------- mode mixing (specW tf32-rounded) ---------------------------
__global__ void modemix_kernel(const float* __restrict__ xcs,
                               const float* __restrict__ wtc,
                               const float* __restrict__ wts,
                               const float* __restrict__ sw0_l,
                               float* __restrict__ specW, float* __restrict__ f0) {
    int b = blockIdx.x;
    int k = blockIdx.y;
    int o = threadIdx.x;
    __shared__ float xc_s[CC], xs_s[CC];
    if (k < 32) {
        xc_s[o] = xcs[(b * 65 + k) * CC + o];
        xs_s[o] = xcs[(b * 65 + 32 + k) * CC + o];
        __syncthreads();
        float fc = 0.f, fs = 0.f;
        #pragma unroll 4
        for (int c = 0; c < CC; c++) {
            float wc = wtc[(k * CC + c) * CC + o];
            float ws = wts[(k * CC + c) * CC + o];
            float a = xc_s[c], s2 = xs_s[c];
            fc += a * wc - s2 * ws;
            fs += s2 * wc + a * ws;
        }
        specW[(b * 64 + k) * CC + o]      = to_tf32( 2.f * fc);
        specW[(b * 64 + 32 + k) * CC + o] = to_tf32(-2.f * fs);
    } else {
        xc_s[o] = xcs[(b * 65 + 64) * CC + o];
        __syncthreads();
        float f = 0.f;
        #pragma unroll 4
        for (int c = 0; c < CC; c++) f += xc_s[c] * sw0_l[c * CC + o];
        f0[b * CC + o] = f;
    }
}

// ---------------- fused combine GEMM — tf32 mma + cp.async -------------------
// 64x128 block tile, 8 warps (2M x 4N, warp 32x32), K=576 in 36 chunks of 16.
// All operands pre-rounded to tf32 by producers — no cvt in this kernel.
__global__ void __launch_bounds__(256, 2)
combine_mma(const float* __restrict__ h, const float* __restrict__ g,
            const float* __restrict__ cosv, const float* __restrict__ sinv,
            const float* __restrict__ wcat, const float* __restrict__ specW,
            const float* __restrict__ f0, const float* __restrict__ wb,
            const float* __restrict__ gb, float* __restrict__ hout,
            int gelu_flag) {
    int b = blockIdx.y;
    int n0 = blockIdx.x * 64;
    int tid = threadIdx.x;
    int warp = tid >> 5, lane = tid & 31;
    int grp = lane >> 2, tig = lane & 3;
    int wm = (warp >> 2) * 32;        // 0 or 32
    int wn = (warp & 3) * 32;         // 0,32,64,96

    __shared__ float As[2][64][36];
    __shared__ float Ws[2][16][136];
    __shared__ float bias_s[128];
    if (tid < 128) bias_s[tid] = wb[tid] + gb[tid] + f0[b * CC + tid];

    float acc[2][4][4];
    #pragma unroll
    for (int i = 0; i < 2; i++)
        #pragma unroll
        for (int j = 0; j < 4; j++)
            #pragma unroll
            for (int q = 0; q < 4; q++) acc[i][j][q] = 0.f;

    // A granule: tid -> (m = tid>>2, k4 = (tid&3)*4); W: 2 granules/thread
    auto issue_tile = [&](int kt, int buf) {
        int kbase = kt * 16;
        {
            int m = tid >> 2;
            int k4 = (tid & 3) * 4;
            int n = n0 + m;
            int k = kbase + k4;
            int nc = (n < NN) ? n : 0;
            int base = b * NN + nc;
            const float* src;
            if (k < 128)      src = h + (size_t)base * 128 + k;
            else if (k < 512) src = g + (size_t)base * 384 + (k - 128);
            else if (k < 544) src = cosv + (size_t)base * 32 + (k - 512);
            else              src = sinv + (size_t)base * 32 + (k - 544);
            cp16(&As[buf][m][k4], src, (n < NN) ? 16 : 0);
        }
        #pragma unroll
        for (int r = 0; r < 2; r++) {
            int l = tid + r * 256;
            int kk = l >> 5;
            int o4 = (l & 31) * 4;
            int k = kbase + kk;
            const float* src = (k < 512) ? wcat + (size_t)k * 128 + o4
                                         : specW + (size_t)(b * 64 + (k - 512)) * 128 + o4;
            cp16(&Ws[buf][kk][o4], src, 16);
        }
    };

    issue_tile(0, 0);
    CP_COMMIT;

    for (int kt = 0; kt < 36; kt++) {
        int cur = kt & 1;
        CP_WAIT0;
        __syncthreads();
        if (kt < 35) {
            issue_tile(kt + 1, cur ^ 1);
            CP_COMMIT;
        }
        #pragma unroll
        for (int k8 = 0; k8 < 2; k8++) {
            int k0 = k8 * 8;
            uint32_t afr[2][4];
            #pragma unroll
            for (int i = 0; i < 2; i++) {
                int r0 = wm + i * 16 + grp;
                afr[i][0] = __float_as_uint(As[cur][r0][k0 + tig]);
                afr[i][1] = __float_as_uint(As[cur][r0 + 8][k0 + tig]);
                afr[i][2] = __float_as_uint(As[cur][r0][k0 + tig + 4]);
                afr[i][3] = __float_as_uint(As[cur][r0 + 8][k0 + tig + 4]);
            }
            uint32_t bfr[4][2];
            #pragma unroll
            for (int j = 0; j < 4; j++) {
                int o = wn + j * 8 + grp;
                bfr[j][0] = __float_as_uint(Ws[cur][k0 + tig][o]);
                bfr[j][1] = __float_as_uint(Ws[cur][k0 + tig + 4][o]);
            }
            #pragma unroll
            for (int i = 0; i < 2; i++)
                #pragma unroll
                for (int j = 0; j < 4; j++)
                    mma_tf32(acc[i][j], afr[i], bfr[j]);
        }
    }
    __syncthreads();

    // epilogue
    #pragma unroll
    for (int i = 0; i < 2; i++) {
        int row0 = wm + i * 16 + grp;
        #pragma unroll
        for (int j = 0; j < 4; j++) {
            int col = wn + j * 8 + tig * 2;
            #pragma unroll
            for (int half = 0; half < 2; half++) {
                int n = n0 + row0 + half * 8;
                if (n < NN) {
                    float v0 = acc[i][j][half * 2 + 0] + bias_s[col];
                    float v1 = acc[i][j][half * 2 + 1] + bias_s[col + 1];
                    if (gelu_flag) {
                        v0 = to_tf32(gelu_f(v0));
                        v1 = to_tf32(gelu_f(v1));
                    }
                    hout[(size_t)(b * NN + n) * CC + col]     = v0;
                    hout[(size_t)(b * NN + n) * CC + col + 1] = v1;
                }
            }
        }
    }
}

// ---------------- final fused MLP GEMM (fp32) --------------------------------
__global__ void __launch_bounds__(256, 2)
final_gemm(const float* __restrict__ h, const float* __restrict__ fc1wt,
           const float* __restrict__ fc1_b, const float* __restrict__ fc2_w,
           const float* __restrict__ fc2_b, float* __restrict__ out) {
    int m0 = blockIdx.x * 128;
    int tid = threadIdx.x;
    int tx = tid & 15, ty = tid >> 4;
    __shared__ float As[128][17];
    __shared__ float Ws[16][128];
    float acc[8][8];
    #pragma unroll
    for (int i = 0; i < 8; i++)
        #pragma unroll
        for (int j = 0; j < 8; j++) acc[i][j] = 0.f;

    for (int kt = 0; kt < 8; kt++) {
        int kbase = kt * 16;
        #pragma unroll
        for (int r = 0; r < 8; r++) {
            int l = tid + r * 256;
            int nl = l >> 4, kk = l & 15;
            As[nl][kk] = h[(m0 + nl) * CC + kbase + kk];
        }
        #pragma unroll
        for (int r = 0; r < 8; r++) {
            int l = tid + r * 256;
            int kk = l >> 7, o = l & 127;
            Ws[kk][o] = fc1wt[(kbase + kk) * CC + o];
        }
        __syncthreads();
        #pragma unroll
        for (int kk = 0; kk < 16; kk++) {
            float a[8];
            #pragma unroll
            for (int i = 0; i < 8; i++) a[i] = As[ty + 16 * i][kk];
            float4 w0 = *(const float4*)&Ws[kk][tx * 4];
            float4 w1 = *(const float4*)&Ws[kk][64 + tx * 4];
            float w[8] = {w0.x, w0.y, w0.z, w0.w, w1.x, w1.y, w1.z, w1.w};
            #pragma unroll
            for (int i = 0; i < 8; i++)
                #pragma unroll
                for (int j = 0; j < 8; j++) acc[i][j] += a[i] * w[j];
        }
        __syncthreads();
    }
    float part[8];
    #pragma unroll
    for (int i = 0; i < 8; i++) {
        float p = 0.f;
        #pragma unroll
        for (int j = 0; j < 8; j++) {
            int o = (j < 4) ? (tx * 4 + j) : (64 + tx * 4 + (j - 4));
            float v = acc[i][j] + fc1_b[o];
            v = gelu_f(v);
            p += v * fc2_w[o];
        }
        part[i] = p;
    }
    __syncthreads();
    #pragma unroll
    for (int i = 0; i < 8; i++) As[ty + 16 * i][tx] = part[i];
    __syncthreads();
    if (tid < 128) {
        float s = 0.f;
        #pragma unroll
        for (int t = 0; t < 16; t++) s += As[tid][t];
        out[m0 + tid] = s + fc2_b[0];
    }
}

// ---------------- launcher ----------------------------------------------------
extern "C" void kernel_launch(void* const* d_in, const int* in_sizes, int n_in,
                              void* d_out, int out_size) {
    const float* x      = (const float*)d_in[0];
    const float* nodes  = (const float*)d_in[2];
    const float* nw     = (const float*)d_in[3];
    const int*   edges  = (const int*)  d_in[4];
    const float* egw    = (const float*)d_in[5];
    const float* modes  = (const float*)d_in[6];
    const float* latent = (const float*)d_in[7];
    const float* fc0_w  = (const float*)d_in[8];
    const float* fc0_b  = (const float*)d_in[9];
    const float* swc    = (const float*)d_in[10];
    const float* sws    = (const float*)d_in[11];
    const float* sw0    = (const float*)d_in[12];
    const float* ww     = (const float*)d_in[13];
    const float* wb     = (const float*)d_in[14];
    const float* gw     = (const float*)d_in[15];
    const float* gb     = (const float*)d_in[16];
    const float* fc1_w  = (const float*)d_in[17];
    const float* fc1_b  = (const float*)d_in[18];
    const float* fc2_w  = (const float*)d_in[19];
    const float* fc2_b  = (const float*)d_in[20];
    float* out = (float*)d_out;

    float *hA, *hB, *g, *cosv, *sinv, *xcs, *specW, *f0, *wcat, *wtc, *wts, *fc1wt, *ew3;
    int *count, *cursor, *offsets, *esrc;
    cudaGetSymbolAddress((void**)&hA,      d_hA);
    cudaGetSymbolAddress((void**)&hB,      d_hB);
    cudaGetSymbolAddress((void**)&g,       d_g);
    cudaGetSymbolAddress((void**)&cosv,    d_cosv);
    cudaGetSymbolAddress((void**)&sinv,    d_sinv);
    cudaGetSymbolAddress((void**)&xcs,     d_xcs);
    cudaGetSymbolAddress((void**)&specW,   d_specW);
    cudaGetSymbolAddress((void**)&f0,      d_f0);
    cudaGetSymbolAddress((void**)&wcat,    d_wcat);
    cudaGetSymbolAddress((void**)&wtc,     d_wtc);
    cudaGetSymbolAddress((void**)&wts,     d_wts);
    cudaGetSymbolAddress((void**)&fc1wt,   d_fc1wt);
    cudaGetSymbolAddress((void**)&count,   d_count);
    cudaGetSymbolAddress((void**)&cursor,  d_cursor);
    cudaGetSymbolAddress((void**)&offsets, d_offsets);
    cudaGetSymbolAddress((void**)&esrc,    d_esrc);
    cudaGetSymbolAddress((void**)&ew3,     d_ew3);

    dim3 t32x8(32, 8);

    // ncu captures launch index 5 (-s 5 -c 1): order so forward_kernel lands there.
    basis_kernel<<<(BB * NN + 127) / 128, 128>>>(nodes, modes, latent, cosv, sinv);   // 0
    fc0_kernel<<<(BB * NN * CC + 255) / 256, 256>>>(x, fc0_w, fc0_b, hA);             // 1
    cudaMemsetAsync(xcs, 0, (size_t)BB * 65 * CC * sizeof(float), 0);                 // 2
    cudaMemsetAsync(count, 0, BB * NN * sizeof(int), 0);                              // 3
    cudaMemsetAsync(cursor, 0, BB * NN * sizeof(int), 0);                             // 4
    forward_kernel<<<dim3(NN / FCHUNK, BB), 512>>>(hA, cosv, sinv, nw, xcs);          // 5 <- profiled

    hist_kernel<<<(BB * EE + 255) / 256, 256>>>(edges, count);
    scan_kernel<<<BB, 1024>>>(count, offsets);
    fill_kernel<<<(BB * EE + 255) / 256, 256>>>(edges, egw, offsets, cursor, esrc, ew3);
    transpose_kernel<<<dim3(4, 4), t32x8>>>(fc1_w, fc1wt, CC, CC, 0);

    float* hin = hA;
    float* hout = hB;
    for (int l = 0; l < 3; l++) {
        if (l > 0) {
            cudaMemsetAsync(xcs, 0, (size_t)BB * 65 * CC * sizeof(float), 0);
            forward_kernel<<<dim3(NN / FCHUNK, BB), 512>>>(hin, cosv, sinv, nw, xcs);
        }
        // swc/sws: [16384][32] -> [32][16384]
        transpose_kernel<<<dim3(1, 512), t32x8>>>(
            swc + (size_t)l * CC * CC * NM, wtc, CC * CC, NM, 0);
        transpose_kernel<<<dim3(1, 512), t32x8>>>(
            sws + (size_t)l * CC * CC * NM, wts, CC * CC, NM, 0);
        modemix_kernel<<<dim3(BB, 33), 128>>>(
            xcs, wtc, wts, sw0 + (size_t)l * CC * CC, specW, f0);
        // wcat rows 0..127 <- ww^T (rounded); rows 128..511 <- gw^T (rounded)
        transpose_kernel<<<dim3(4, 4), t32x8>>>(
            ww + (size_t)l * CC * CC, wcat, CC, CC, 1);
        transpose_kernel<<<dim3(12, 4), t32x8>>>(
            gw + (size_t)l * CC * 384, wcat + 128 * CC, CC, 384, 1);
        gather_kernel<<<dim3(NN / NPB, BB), 128>>>(hin, offsets, esrc, ew3, g);
        combine_mma<<<dim3((NN + 63) / 64, BB), 256>>>(
            hin, g, cosv, sinv, wcat, specW, f0,
            wb + l * CC, gb + l * CC, hout, (l < 2) ? 1 : 0);
        float* t = hin; hin = hout; hout = t;
    }
    final_gemm<<<(BB * NN) / 128, 256>>>(hin, fc1wt, fc1_b, fc2_w, fc2_b, out);
}

// round 5
// speedup vs baseline: 5.1478x; 1.0367x over previous
#include <cuda_runtime.h>
#include <math.h>
#include <stdint.h>

#define BB 4
#define NN 20000
#define EE 100000
#define CC 128
#define NM 32

// ---------------- scratch (static device globals; no allocation) -------------
__device__ float d_hA[BB * NN * CC];
__device__ float d_hB[BB * NN * CC];
__device__ float d_g[(size_t)BB * NN * 384];
__device__ float d_cosv[BB * NN * NM];
__device__ float d_sinv[BB * NN * NM];
__device__ float d_xcs[BB * 65 * CC];
__device__ float d_specW[BB * 64 * CC];
__device__ float d_f0[BB * CC];
__device__ float d_wcat[512 * CC];
__device__ float d_wtc[NM * CC * CC];     // [k][c][o]
__device__ float d_wts[NM * CC * CC];     // [k][c][o]
__device__ float d_fc1wt[CC * CC];        // [c][j]
// CSR scratch
__device__ int   d_count[BB * NN];
__device__ int   d_cursor[BB * NN];
__device__ int   d_offsets[BB * (NN + 1)];
__device__ int   d_esrc[BB * EE];
__device__ float d_ew3[(size_t)BB * EE * 3];

__device__ __forceinline__ float gelu_f(float v) {
    return 0.5f * v * (1.f + erff(v * 0.70710678118654752f));
}

__device__ __forceinline__ float to_tf32(float x) {
    uint32_t u;
    asm("cvt.rna.tf32.f32 %0, %1;" : "=r"(u) : "f"(x));
    return __uint_as_float(u);
}

__device__ __forceinline__ void mma_tf32(float* d, const uint32_t* a, const uint32_t* b) {
    asm volatile(
        "mma.sync.aligned.m16n8k8.row.col.f32.tf32.tf32.f32 "
        "{%0,%1,%2,%3}, {%4,%5,%6,%7}, {%8,%9}, {%0,%1,%2,%3};"
        : "+f"(d[0]), "+f"(d[1]), "+f"(d[2]), "+f"(d[3])
        : "r"(a[0]), "r"(a[1]), "r"(a[2]), "r"(a[3]), "r"(b[0]), "r"(b[1]));
}

__device__ __forceinline__ void cp16(void* smem_dst, const void* gsrc, int src_bytes) {
    uint32_t d = (uint32_t)__cvta_generic_to_shared(smem_dst);
    asm volatile("cp.async.cg.shared.global [%0], [%1], 16, %2;"
                 :: "r"(d), "l"(gsrc), "r"(src_bytes));
}
#define CP_COMMIT asm volatile("cp.async.commit_group;")
#define CP_WAIT(n) asm volatile("cp.async.wait_group %0;" :: "n"(n))

// ---------------- basis (tf32-rounded outputs) -------------------------------
__global__ void basis_kernel(const float* __restrict__ nodes,
                             const float* __restrict__ modes,
                             const float* __restrict__ latent,
                             float* __restrict__ cosv, float* __restrict__ sinv) {
    int idx = blockIdx.x * blockDim.x + threadIdx.x;
    if (idx >= BB * NN) return;
    float il0 = 0.5f + 1.5f / (1.f + expf(-latent[0]));
    float il1 = 0.5f + 1.5f / (1.f + expf(-latent[1]));
    float il2 = 0.5f + 1.5f / (1.f + expf(-latent[2]));
    float n0 = nodes[idx * 3 + 0];
    float n1 = nodes[idx * 3 + 1];
    float n2 = nodes[idx * 3 + 2];
    #pragma unroll
    for (int k = 0; k < NM; k++) {
        float t = n0 * modes[k * 3 + 0] * il0
                + n1 * modes[k * 3 + 1] * il1
                + n2 * modes[k * 3 + 2] * il2;
        float s, c;
        sincosf(t, &s, &c);
        cosv[idx * NM + k] = to_tf32(c);
        sinv[idx * NM + k] = to_tf32(s);
    }
}

// ---------------- fc0 (tf32-rounded) -----------------------------------------
__global__ void fc0_kernel(const float* __restrict__ x, const float* __restrict__ w,
                           const float* __restrict__ bias, float* __restrict__ h) {
    int idx = blockIdx.x * blockDim.x + threadIdx.x;
    if (idx >= BB * NN * CC) return;
    int c = idx & 127;
    int node = idx >> 7;
    float v = bias[c] + x[node * 3 + 0] * w[c * 3 + 0]
                      + x[node * 3 + 1] * w[c * 3 + 1]
                      + x[node * 3 + 2] * w[c * 3 + 2];
    h[idx] = to_tf32(v);
}

// ---------------- CSR build --------------------------------------------------
__global__ void hist_kernel(const int* __restrict__ edges, int* __restrict__ count) {
    int idx = blockIdx.x * blockDim.x + threadIdx.x;
    if (idx >= BB * EE) return;
    int b = idx / EE;
    int tgt = edges[idx * 2 + 0];
    atomicAdd(&count[b * NN + tgt], 1);
}

__global__ void scan_kernel(const int* __restrict__ count, int* __restrict__ offsets) {
    int b = blockIdx.x;
    int t = threadIdx.x;              // 1024
    __shared__ int sums[1024];
    const int CH = 20;
    int base = t * CH;
    int s = 0;
    for (int i = 0; i < CH; i++) {
        int n = base + i;
        if (n < NN) s += count[b * NN + n];
    }
    sums[t] = s;
    __syncthreads();
    for (int off = 1; off < 1024; off <<= 1) {
        int v = (t >= off) ? sums[t - off] : 0;
        __syncthreads();
        sums[t] += v;
        __syncthreads();
    }
    int run = (t == 0) ? 0 : sums[t - 1];
    for (int i = 0; i < CH; i++) {
        int n = base + i;
        if (n < NN) {
            offsets[b * (NN + 1) + n] = run;
            run += count[b * NN + n];
        }
    }
    if (t == 1023) offsets[b * (NN + 1) + NN] = sums[1023];
}

__global__ void fill_kernel(const int* __restrict__ edges, const float* __restrict__ egw,
                            const int* __restrict__ offsets, int* __restrict__ cursor,
                            int* __restrict__ esrc, float* __restrict__ ew3) {
    int idx = blockIdx.x * blockDim.x + threadIdx.x;
    if (idx >= BB * EE) return;
    int b = idx / EE;
    int tgt = edges[idx * 2 + 0];
    int src = edges[idx * 2 + 1];
    int pos = offsets[b * (NN + 1) + tgt] + atomicAdd(&cursor[b * NN + tgt], 1);
    int gp = b * EE + pos;
    esrc[gp] = src;
    ew3[(size_t)gp * 3 + 0] = egw[(size_t)idx * 3 + 0];
    ew3[(size_t)gp * 3 + 1] = egw[(size_t)idx * 3 + 1];
    ew3[(size_t)gp * 3 + 2] = egw[(size_t)idx * 3 + 2];
}

// ---------------- gradient gather: smem edge staging, 8 nodes/block ----------
#define NPB 8
#define ECH 128
__global__ void __launch_bounds__(128)
gather_kernel(const float* __restrict__ h,
              const int* __restrict__ offsets,
              const int* __restrict__ esrc,
              const float* __restrict__ ew3,
              float* __restrict__ g) {
    int b = blockIdx.y;
    int c = threadIdx.x;   // 128
    int n0 = blockIdx.x * NPB;
    __shared__ int s_off[NPB + 1];
    __shared__ int s_src[ECH];
    __shared__ float s_w[ECH * 3];
    if (c <= NPB) s_off[c] = offsets[b * (NN + 1) + n0 + c];
    __syncthreads();
    int e0 = s_off[0], e1 = s_off[NPB];
    const float* hb = h + (size_t)(b * NN) * CC;
    float ht[NPB];
    float acc[NPB][3];
    #pragma unroll
    for (int i = 0; i < NPB; i++) {
        ht[i] = hb[(n0 + i) * CC + c];
        acc[i][0] = acc[i][1] = acc[i][2] = 0.f;
    }
    size_t ebase = (size_t)b * EE;
    for (int cbase = e0; cbase < e1; cbase += ECH) {
        int cnt = min(ECH, e1 - cbase);
        __syncthreads();
        if (c < cnt) s_src[c] = esrc[ebase + cbase + c];
        for (int l = c; l < cnt * 3; l += 128)
            s_w[l] = ew3[(ebase + cbase) * 3 + l];
        __syncthreads();
        #pragma unroll
        for (int i = 0; i < NPB; i++) {
            int lo = max(s_off[i] - cbase, 0);
            int hi = min(s_off[i + 1] - cbase, cnt);
            for (int j = lo; j < hi; j++) {
                float hs = hb[s_src[j] * CC + c];
                float d = hs - ht[i];
                acc[i][0] += s_w[j * 3 + 0] * d;
                acc[i][1] += s_w[j * 3 + 1] * d;
                acc[i][2] += s_w[j * 3 + 2] * d;
            }
        }
    }
    #pragma unroll
    for (int i = 0; i < NPB; i++) {
        size_t gb_ = (size_t)(b * NN + n0 + i) * 384 + c * 3;
        g[gb_ + 0] = to_tf32(acc[i][0]);
        g[gb_ + 1] = to_tf32(acc[i][1]);
        g[gb_ + 2] = to_tf32(acc[i][2]);
    }
}

// ---------------- forward spectral transform (256 thr, occ 3) ----------------
#define FCHUNK 50
__global__ void __launch_bounds__(256)
forward_kernel(const float* __restrict__ h,
               const float* __restrict__ cosv,
               const float* __restrict__ sinv,
               const float* __restrict__ nw,
               float* __restrict__ xcs) {
    int b = blockIdx.y;
    int tid = threadIdx.x;           // 256
    int sub = tid >> 7;              // 0/1
    int c = tid & 127;
    int n0 = blockIdx.x * FCHUNK;
    float acc[65];
    #pragma unroll
    for (int r = 0; r < 65; r++) acc[r] = 0.f;
    __shared__ float sb[2][65];
    __shared__ float red[16][128];
    for (int base = n0; base < n0 + FCHUNK; base += 2) {
        for (int l = tid; l < 130; l += 256) {
            int i = l / 65;
            int r = l - i * 65;
            int node = base + i;
            float w = nw[b * NN + node];
            float v;
            if (r < 32)      v = w * cosv[(b * NN + node) * NM + r];
            else if (r < 64) v = w * sinv[(b * NN + node) * NM + (r - 32)];
            else             v = w;
            sb[i][r] = v;
        }
        __syncthreads();
        float hv = h[(b * NN + base + sub) * CC + c];
        #pragma unroll
        for (int r = 0; r < 65; r++) acc[r] += hv * sb[sub][r];
        __syncthreads();
    }
    for (int r0 = 0; r0 < 65; r0 += 16) {
        int nr = min(16, 65 - r0);
        if (sub == 1)
            for (int rr = 0; rr < nr; rr++) red[rr][c] = acc[r0 + rr];
        __syncthreads();
        if (sub == 0)
            for (int rr = 0; rr < nr; rr++)
                atomicAdd(&xcs[(b * 65 + r0 + rr) * CC + c], acc[r0 + rr] + red[rr][c]);
        __syncthreads();
    }
}

// ---------------- generic tiled transpose: src[R][C] -> dst[C][R] ------------
__global__ void transpose_kernel(const float* __restrict__ src, float* __restrict__ dst,
                                 int R, int C, int do_round) {
    __shared__ float tile[32][33];
    int c0 = blockIdx.x * 32;
    int r0 = blockIdx.y * 32;
    int tx = threadIdx.x, ty = threadIdx.y;   // 32 x 8
    #pragma unroll
    for (int i = 0; i < 4; i++) {
        int r = r0 + ty + i * 8;
        int c = c0 + tx;
        if (r < R && c < C) tile[ty + i * 8][tx] = src[r * C + c];
    }
    __syncthreads();
    #pragma unroll
    for (int i = 0; i < 4; i++) {
        int c = c0 + ty + i * 8;
        int r = r0 + tx;
        if (r < R && c < C) {
            float v = tile[tx][ty + i * 8];
            dst[c * R + r] = do_round ? to_tf32(v) : v;
        }
    }
}

// ---------------- mode mixing (specW tf32-rounded) ---------------------------
__global__ void modemix_kernel(const float* __restrict__ xcs,
                               const float* __restrict__ wtc,
                               const float* __restrict__ wts,
                               const float* __restrict__ sw0_l,
                               float* __restrict__ specW, float* __restrict__ f0) {
    int b = blockIdx.x;
    int k = blockIdx.y;
    int o = threadIdx.x;
    __shared__ float xc_s[CC], xs_s[CC];
    if (k < 32) {
        xc_s[o] = xcs[(b * 65 + k) * CC + o];
        xs_s[o] = xcs[(b * 65 + 32 + k) * CC + o];
        __syncthreads();
        float fc = 0.f, fs = 0.f;
        #pragma unroll 4
        for (int c = 0; c < CC; c++) {
            float wc = wtc[(k * CC + c) * CC + o];
            float ws = wts[(k * CC + c) * CC + o];
            float a = xc_s[c], s2 = xs_s[c];
            fc += a * wc - s2 * ws;
            fs += s2 * wc + a * ws;
        }
        specW[(b * 64 + k) * CC + o]      = to_tf32( 2.f * fc);
        specW[(b * 64 + 32 + k) * CC + o] = to_tf32(-2.f * fs);
    } else {
        xc_s[o] = xcs[(b * 65 + 64) * CC + o];
        __syncthreads();
        float f = 0.f;
        #pragma unroll 4
        for (int c = 0; c < CC; c++) f += xc_s[c] * sw0_l[c * CC + o];
        f0[b * CC + o] = f;
    }
}

// ---------------- fused combine GEMM — tf32 mma, 4-stage cp.async ------------
// 64x128 tile, 8 warps (2M x 4N), K=576 in 36 chunks of 16. Dynamic smem.
#define CSTAGES 4
#define AS_ELEMS (64 * 36)
#define WS_ELEMS (16 * 136)
#define CSMEM_BYTES ((CSTAGES * (AS_ELEMS + WS_ELEMS) + 128) * 4)
__global__ void __launch_bounds__(256, 3)
combine_mma(const float* __restrict__ h, const float* __restrict__ g,
            const float* __restrict__ cosv, const float* __restrict__ sinv,
            const float* __restrict__ wcat, const float* __restrict__ specW,
            const float* __restrict__ f0, const float* __restrict__ wb,
            const float* __restrict__ gb, float* __restrict__ hout,
            int gelu_flag) {
    extern __shared__ float dsm[];
    float (*As)[64][36] = (float(*)[64][36])dsm;
    float (*Ws)[16][136] = (float(*)[16][136])(dsm + CSTAGES * AS_ELEMS);
    float* bias_s = dsm + CSTAGES * (AS_ELEMS + WS_ELEMS);

    int b = blockIdx.y;
    int n0 = blockIdx.x * 64;
    int tid = threadIdx.x;
    int warp = tid >> 5, lane = tid & 31;
    int grp = lane >> 2, tig = lane & 3;
    int wm = (warp >> 2) * 32;
    int wn = (warp & 3) * 32;

    if (tid < 128) bias_s[tid] = wb[tid] + gb[tid] + f0[b * CC + tid];

    float acc[2][4][4];
    #pragma unroll
    for (int i = 0; i < 2; i++)
        #pragma unroll
        for (int j = 0; j < 4; j++)
            #pragma unroll
            for (int q = 0; q < 4; q++) acc[i][j][q] = 0.f;

    const float* hb = h + (size_t)(b * NN) * 128;
    const float* gbp = g + (size_t)(b * NN) * 384;
    const float* cb = cosv + (size_t)(b * NN) * 32;
    const float* sb2 = sinv + (size_t)(b * NN) * 32;
    const float* spb = specW + (size_t)(b * 64) * 128;

    auto issue_tile = [&](int kt, int buf) {
        int kbase = kt * 16;
        {
            int m = tid >> 2;
            int k4 = (tid & 3) * 4;
            int n = n0 + m;
            int nc = (n < NN) ? n : 0;
            int k = kbase + k4;
            const float* src;
            if (k < 128)      src = hb + (size_t)nc * 128 + k;
            else if (k < 512) src = gbp + (size_t)nc * 384 + (k - 128);
            else if (k < 544) src = cb + (size_t)nc * 32 + (k - 512);
            else              src = sb2 + (size_t)nc * 32 + (k - 544);
            cp16(&As[buf][m][k4], src, (n < NN) ? 16 : 0);
        }
        #pragma unroll
        for (int r = 0; r < 2; r++) {
            int l = tid + r * 256;
            int kk = l >> 5;
            int o4 = (l & 31) * 4;
            int k = kbase + kk;
            const float* src = (k < 512) ? wcat + (size_t)k * 128 + o4
                                         : spb + (size_t)(k - 512) * 128 + o4;
            cp16(&Ws[buf][kk][o4], src, 16);
        }
    };

    issue_tile(0, 0); CP_COMMIT;
    issue_tile(1, 1); CP_COMMIT;
    issue_tile(2, 2); CP_COMMIT;

    for (int kt = 0; kt < 36; kt++) {
        int cur = kt & 3;
        if (kt <= 33) CP_WAIT(2);
        else if (kt == 34) CP_WAIT(1);
        else CP_WAIT(0);
        __syncthreads();
        if (kt < 33) {
            issue_tile(kt + 3, (kt + 3) & 3);
            CP_COMMIT;
        }
        #pragma unroll
        for (int k8 = 0; k8 < 2; k8++) {
            int k0 = k8 * 8;
            uint32_t afr[2][4];
            #pragma unroll
            for (int i = 0; i < 2; i++) {
                int r0 = wm + i * 16 + grp;
                afr[i][0] = __float_as_uint(As[cur][r0][k0 + tig]);
                afr[i][1] = __float_as_uint(As[cur][r0 + 8][k0 + tig]);
                afr[i][2] = __float_as_uint(As[cur][r0][k0 + tig + 4]);
                afr[i][3] = __float_as_uint(As[cur][r0 + 8][k0 + tig + 4]);
            }
            uint32_t bfr[4][2];
            #pragma unroll
            for (int j = 0; j < 4; j++) {
                int o = wn + j * 8 + grp;
                bfr[j][0] = __float_as_uint(Ws[cur][k0 + tig][o]);
                bfr[j][1] = __float_as_uint(Ws[cur][k0 + tig + 4][o]);
            }
            #pragma unroll
            for (int i = 0; i < 2; i++)
                #pragma unroll
                for (int j = 0; j < 4; j++)
                    mma_tf32(acc[i][j], afr[i], bfr[j]);
        }
        __syncthreads();
    }

    // epilogue
    #pragma unroll
    for (int i = 0; i < 2; i++) {
        int row0 = wm + i * 16 + grp;
        #pragma unroll
        for (int j = 0; j < 4; j++) {
            int col = wn + j * 8 + tig * 2;
            #pragma unroll
            for (int half = 0; half < 2; half++) {
                int n = n0 + row0 + half * 8;
                if (n < NN) {
                    float v0 = acc[i][j][half * 2 + 0] + bias_s[col];
                    float v1 = acc[i][j][half * 2 + 1] + bias_s[col + 1];
                    if (gelu_flag) {
                        v0 = to_tf32(gelu_f(v0));
                        v1 = to_tf32(gelu_f(v1));
                    }
                    hout[(size_t)(b * NN + n) * CC + col]     = v0;
                    hout[(size_t)(b * NN + n) * CC + col + 1] = v1;
                }
            }
        }
    }
}

// ---------------- final fused MLP GEMM (fp32) --------------------------------
__global__ void __launch_bounds__(256, 2)
final_gemm(const float* __restrict__ h, const float* __restrict__ fc1wt,
           const float* __restrict__ fc1_b, const float* __restrict__ fc2_w,
           const float* __restrict__ fc2_b, float* __restrict__ out) {
    int m0 = blockIdx.x * 128;
    int tid = threadIdx.x;
    int tx = tid & 15, ty = tid >> 4;
    __shared__ float As[128][17];
    __shared__ float Ws[16][128];
    float acc[8][8];
    #pragma unroll
    for (int i = 0; i < 8; i++)
        #pragma unroll
        for (int j = 0; j < 8; j++) acc[i][j] = 0.f;

    for (int kt = 0; kt < 8; kt++) {
        int kbase = kt * 16;
        #pragma unroll
        for (int r = 0; r < 8; r++) {
            int l = tid + r * 256;
            int nl = l >> 4, kk = l & 15;
            As[nl][kk] = h[(m0 + nl) * CC + kbase + kk];
        }
        #pragma unroll
        for (int r = 0; r < 8; r++) {
            int l = tid + r * 256;
            int kk = l >> 7, o = l & 127;
            Ws[kk][o] = fc1wt[(kbase + kk) * CC + o];
        }
        __syncthreads();
        #pragma unroll
        for (int kk = 0; kk < 16; kk++) {
            float a[8];
            #pragma unroll
            for (int i = 0; i < 8; i++) a[i] = As[ty + 16 * i][kk];
            float4 w0 = *(const float4*)&Ws[kk][tx * 4];
            float4 w1 = *(const float4*)&Ws[kk][64 + tx * 4];
            float w[8] = {w0.x, w0.y, w0.z, w0.w, w1.x, w1.y, w1.z, w1.w};
            #pragma unroll
            for (int i = 0; i < 8; i++)
                #pragma unroll
                for (int j = 0; j < 8; j++) acc[i][j] += a[i] * w[j];
        }
        __syncthreads();
    }
    float part[8];
    #pragma unroll
    for (int i = 0; i < 8; i++) {
        float p = 0.f;
        #pragma unroll
        for (int j = 0; j < 8; j++) {
            int o = (j < 4) ? (tx * 4 + j) : (64 + tx * 4 + (j - 4));
            float v = acc[i][j] + fc1_b[o];
            v = gelu_f(v);
            p += v * fc2_w[o];
        }
        part[i] = p;
    }
    __syncthreads();
    #pragma unroll
    for (int i = 0; i < 8; i++) As[ty + 16 * i][tx] = part[i];
    __syncthreads();
    if (tid < 128) {
        float s = 0.f;
        #pragma unroll
        for (int t = 0; t < 16; t++) s += As[tid][t];
        out[m0 + tid] = s + fc2_b[0];
    }
}

// ---------------- launcher ----------------------------------------------------
extern "C" void kernel_launch(void* const* d_in, const int* in_sizes, int n_in,
                              void* d_out, int out_size) {
    const float* x      = (const float*)d_in[0];
    const float* nodes  = (const float*)d_in[2];
    const float* nw     = (const float*)d_in[3];
    const int*   edges  = (const int*)  d_in[4];
    const float* egw    = (const float*)d_in[5];
    const float* modes  = (const float*)d_in[6];
    const float* latent = (const float*)d_in[7];
    const float* fc0_w  = (const float*)d_in[8];
    const float* fc0_b  = (const float*)d_in[9];
    const float* swc    = (const float*)d_in[10];
    const float* sws    = (const float*)d_in[11];
    const float* sw0    = (const float*)d_in[12];
    const float* ww     = (const float*)d_in[13];
    const float* wb     = (const float*)d_in[14];
    const float* gw     = (const float*)d_in[15];
    const float* gb     = (const float*)d_in[16];
    const float* fc1_w  = (const float*)d_in[17];
    const float* fc1_b  = (const float*)d_in[18];
    const float* fc2_w  = (const float*)d_in[19];
    const float* fc2_b  = (const float*)d_in[20];
    float* out = (float*)d_out;

    float *hA, *hB, *g, *cosv, *sinv, *xcs, *specW, *f0, *wcat, *wtc, *wts, *fc1wt, *ew3;
    int *count, *cursor, *offsets, *esrc;
    cudaGetSymbolAddress((void**)&hA,      d_hA);
    cudaGetSymbolAddress((void**)&hB,      d_hB);
    cudaGetSymbolAddress((void**)&g,       d_g);
    cudaGetSymbolAddress((void**)&cosv,    d_cosv);
    cudaGetSymbolAddress((void**)&sinv,    d_sinv);
    cudaGetSymbolAddress((void**)&xcs,     d_xcs);
    cudaGetSymbolAddress((void**)&specW,   d_specW);
    cudaGetSymbolAddress((void**)&f0,      d_f0);
    cudaGetSymbolAddress((void**)&wcat,    d_wcat);
    cudaGetSymbolAddress((void**)&wtc,     d_wtc);
    cudaGetSymbolAddress((void**)&wts,     d_wts);
    cudaGetSymbolAddress((void**)&fc1wt,   d_fc1wt);
    cudaGetSymbolAddress((void**)&count,   d_count);
    cudaGetSymbolAddress((void**)&cursor,  d_cursor);
    cudaGetSymbolAddress((void**)&offsets, d_offsets);
    cudaGetSymbolAddress((void**)&esrc,    d_esrc);
    cudaGetSymbolAddress((void**)&ew3,     d_ew3);

    cudaFuncSetAttribute(combine_mma, cudaFuncAttributeMaxDynamicSharedMemorySize,
                         CSMEM_BYTES);

    dim3 t32x8(32, 8);

    // Order chosen so profile index 5/6 lands on gather (layer 0).
    fc0_kernel<<<(BB * NN * CC + 255) / 256, 256>>>(x, fc0_w, fc0_b, hA);         // 0
    cudaMemsetAsync(count, 0, BB * NN * sizeof(int), 0);                          // 1
    cudaMemsetAsync(cursor, 0, BB * NN * sizeof(int), 0);                         // 2
    hist_kernel<<<(BB * EE + 255) / 256, 256>>>(edges, count);                    // 3
    scan_kernel<<<BB, 1024>>>(count, offsets);                                    // 4
    fill_kernel<<<(BB * EE + 255) / 256, 256>>>(edges, egw, offsets, cursor, esrc, ew3); // 5
    gather_kernel<<<dim3(NN / NPB, BB), 128>>>(hA, offsets, esrc, ew3, g);        // 6

    basis_kernel<<<(BB * NN + 127) / 128, 128>>>(nodes, modes, latent, cosv, sinv);
    cudaMemsetAsync(xcs, 0, (size_t)BB * 65 * CC * sizeof(float), 0);
    forward_kernel<<<dim3(NN / FCHUNK, BB), 256>>>(hA, cosv, sinv, nw, xcs);
    transpose_kernel<<<dim3(4, 4), t32x8>>>(fc1_w, fc1wt, CC, CC, 0);

    float* hin = hA;
    float* hout = hB;
    for (int l = 0; l < 3; l++) {
        if (l > 0) {
            cudaMemsetAsync(xcs, 0, (size_t)BB * 65 * CC * sizeof(float), 0);
            forward_kernel<<<dim3(NN / FCHUNK, BB), 256>>>(hin, cosv, sinv, nw, xcs);
            gather_kernel<<<dim3(NN / NPB, BB), 128>>>(hin, offsets, esrc, ew3, g);
        }
        transpose_kernel<<<dim3(1, 512), t32x8>>>(
            swc + (size_t)l * CC * CC * NM, wtc, CC * CC, NM, 0);
        transpose_kernel<<<dim3(1, 512), t32x8>>>(
            sws + (size_t)l * CC * CC * NM, wts, CC * CC, NM, 0);
        modemix_kernel<<<dim3(BB, 33), 128>>>(
            xcs, wtc, wts, sw0 + (size_t)l * CC * CC, specW, f0);
        transpose_kernel<<<dim3(4, 4), t32x8>>>(
            ww + (size_t)l * CC * CC, wcat, CC, CC, 1);
        transpose_kernel<<<dim3(12, 4), t32x8>>>(
            gw + (size_t)l * CC * 384, wcat + 128 * CC, CC, 384, 1);
        combine_mma<<<dim3((NN + 63) / 64, BB), 256, CSMEM_BYTES>>>(
            hin, g, cosv, sinv, wcat, specW, f0,
            wb + l * CC, gb + l * CC, hout, (l < 2) ? 1 : 0);
        float* t = hin; hin = hout; hout = t;
    }
    final_gemm<<<(BB * NN) / 128, 256>>>(hin, fc1wt, fc1_b, fc2_w, fc2_b, out);
}